// round 5
// baseline (speedup 1.0000x reference)
#include <cuda_runtime.h>
#include <cuda_bf16.h>

// Problem constants (fixed shapes per metadata):
//   x:      (16, 64, 128, 128) f32
//   weight: (16, 64, 64, 3, 3) f32
//   bias:   (16, 64)           f32
//   out:    (16, 64, 126, 126) f32  (valid conv)
#define B_   16
#define CI_  64
#define CO_  64
#define H_   128
#define W_   128
#define KH_  3
#define KW_  3
#define HO_  126
#define WO_  126

// Block tiling: one batch, 8 output channels, 16 x 64 output tile.
#define OCB  8     // output channels per block
#define TH   16    // output rows per block
#define TW   64    // output cols per block (2 cols per thread, 32 threads in x)
#define XS_ROWS (TH + 2)        // 18
#define XS_COLS 68              // 66 needed, padded to 68
#define XS_ELEMS (XS_ROWS * XS_COLS)   // 1224
#define NLOAD 5                 // ceil(1224 / 256)

// Packed f32x2 FMA: d.lo += a.lo*b.lo ; d.hi += a.hi*b.hi  (sm_100+ PTX)
__device__ __forceinline__ void fma2(unsigned long long& d,
                                     unsigned long long a,
                                     unsigned long long b) {
    asm("fma.rn.f32x2 %0, %1, %2, %0;" : "+l"(d) : "l"(a), "l"(b));
}

__device__ __forceinline__ unsigned long long splat2(float v) {
    unsigned long long bits = (unsigned long long)__float_as_uint(v);
    return bits | (bits << 32);
}

__global__ void __launch_bounds__(256, 2)
dynconv2d_kernel(const float* __restrict__ x,
                 const float* __restrict__ wgt,
                 const float* __restrict__ bias,
                 float* __restrict__ out) {
    // Shared: pre-splatted weights for this (b, oc-block) across ALL c_in,
    // plus one input tile (single buffer; LDG prefetch hides global latency).
    __shared__ unsigned long long ws[OCB * CI_ * 9];   // 36,864 B
    __shared__ __align__(16) float xs[XS_ELEMS];       //  4,896 B

    const int tx  = threadIdx.x;            // 0..31 -> 2 output cols each
    const int ty  = threadIdx.y;            // 0..7  -> 2 output rows each
    const int tid = ty * 32 + tx;

    const int wt  = blockIdx.x;             // 0..1   (W tiles)
    const int ht  = blockIdx.y;             // 0..7   (H tiles)
    const int z   = blockIdx.z;             // 0..127 (b * oc-tiles)
    const int b   = z >> 3;
    const int ocb = (z & 7) * OCB;
    const int h0  = ht * TH;
    const int w0  = wt * TW;

    // ---- Load + splat all weights for this block (4608 scalars, 18/thread) ----
    {
        const float* wg = wgt + (size_t)(b * CO_ + ocb) * CI_ * 9;
        #pragma unroll
        for (int k = 0; k < 18; k++) {
            int idx = tid + k * 256;          // layout: (oc*CI + ci)*9 + tap
            ws[idx] = splat2(wg[idx]);
        }
    }

    // ---- Accumulators initialized with bias ----
    unsigned long long acc[OCB][2];
    #pragma unroll
    for (int oc = 0; oc < OCB; oc++) {
        unsigned long long bv = splat2(bias[b * CO_ + ocb + oc]);
        acc[oc][0] = bv;
        acc[oc][1] = bv;
    }

    // ---- Precompute input-tile loader offsets (constant across c_in) ----
    int gofs[NLOAD], sofs[NLOAD];
    bool lval[NLOAD];
    #pragma unroll
    for (int k = 0; k < NLOAD; k++) {
        int i = tid + k * 256;
        int r = i / XS_COLS;
        int c = i - r * XS_COLS;
        lval[k] = (i < XS_ELEMS);
        int gh = min(h0 + r, H_ - 1);        // clamp; clamped rows/cols feed
        int gw = min(w0 + c, W_ - 1);        // only predicated-off outputs
        gofs[k] = gh * W_ + gw;
        sofs[k] = i;
    }

    const float* xb = x + (size_t)b * CI_ * H_ * W_;

    // ---- Prologue: stage input tile for ci = 0 ----
    float pf[NLOAD];
    #pragma unroll
    for (int k = 0; k < NLOAD; k++) if (lval[k]) pf[k] = xb[gofs[k]];
    #pragma unroll
    for (int k = 0; k < NLOAD; k++) if (lval[k]) xs[sofs[k]] = pf[k];
    __syncthreads();

    // ---- Main loop over input channels ----
    for (int ci = 0; ci < CI_; ci++) {
        // Prefetch next tile into registers (latency hidden under compute).
        if (ci + 1 < CI_) {
            const float* xn = xb + (size_t)(ci + 1) * (H_ * W_);
            #pragma unroll
            for (int k = 0; k < NLOAD; k++) if (lval[k]) pf[k] = xn[gofs[k]];
        }

        // Load 4 input rows x 3 column-pairs for this thread.
        // pa = (c0,c1), pb = (c2,c3); mid = (c1,c2) via 64-bit shift merge.
        unsigned long long in[4][3];
        #pragma unroll
        for (int ir = 0; ir < 4; ir++) {
            const unsigned long long* rp = (const unsigned long long*)
                (xs + (ty * 2 + ir) * XS_COLS + 2 * tx);
            unsigned long long pa = rp[0];
            unsigned long long pb = rp[1];
            in[ir][0] = pa;
            in[ir][1] = (pa >> 32) | (pb << 32);
            in[ir][2] = pb;
        }

        // 8 oc x 2 rows x 9 taps = 144 packed FMAs per thread per ci.
        #pragma unroll
        for (int oc = 0; oc < OCB; oc++) {
            unsigned long long wv[9];
            #pragma unroll
            for (int t = 0; t < 9; t++)
                wv[t] = ws[(oc * CI_ + ci) * 9 + t];   // broadcast LDS.64
            #pragma unroll
            for (int r = 0; r < 2; r++)
                #pragma unroll
                for (int kh = 0; kh < 3; kh++)
                    #pragma unroll
                    for (int kw = 0; kw < 3; kw++)
                        fma2(acc[oc][r], wv[kh * 3 + kw], in[r + kh][kw]);
        }

        // Commit prefetched tile for the next iteration.
        if (ci + 1 < CI_) {
            __syncthreads();   // all readers of xs are done
            #pragma unroll
            for (int k = 0; k < NLOAD; k++) if (lval[k]) xs[sofs[k]] = pf[k];
            __syncthreads();   // tile visible to all
        }
    }

    // ---- Store (float2 per accumulator; bounds-predicated) ----
    const int ow = w0 + 2 * tx;
    if (ow < WO_) {   // ow even, so ow valid => ow+1 valid too (ow <= 124)
        #pragma unroll
        for (int oc = 0; oc < OCB; oc++) {
            #pragma unroll
            for (int r = 0; r < 2; r++) {
                int oh = h0 + ty * 2 + r;
                if (oh < HO_) {
                    float2 v;
                    asm("mov.b64 {%0, %1}, %2;"
                        : "=f"(v.x), "=f"(v.y) : "l"(acc[oc][r]));
                    *(float2*)(out + ((size_t)(b * CO_ + ocb + oc) * HO_ + oh) * WO_ + ow) = v;
                }
            }
        }
    }
}

extern "C" void kernel_launch(void* const* d_in, const int* in_sizes, int n_in,
                              void* d_out, int out_size) {
    (void)in_sizes; (void)n_in; (void)out_size;
    const float* x    = (const float*)d_in[0];
    const float* wgt  = (const float*)d_in[1];
    const float* bias = (const float*)d_in[2];
    float* out        = (float*)d_out;

    dim3 block(32, 8, 1);
    dim3 grid(WO_ > TW ? 2 : 1,          // 2 W tiles (covers 128 cols)
              (HO_ + TH - 1) / TH,       // 8 H tiles
              B_ * (CO_ / OCB));         // 128 (batch x oc-tiles)
    dynconv2d_kernel<<<grid, block>>>(x, wgt, bias, out);
}

// round 6
// speedup vs baseline: 1.0890x; 1.0890x over previous
#include <cuda_runtime.h>
#include <cuda_bf16.h>

// Shapes (fixed):
//   x:      (16, 64, 128, 128) f32
//   weight: (16, 64, 64, 3, 3) f32
//   bias:   (16, 64)           f32
//   out:    (16, 64, 126, 126) f32  (valid conv)
#define B_   16
#define CI_  64
#define CO_  64
#define H_   128
#define W_   128
#define HO_  126
#define WO_  126

// Block tiling: one batch, 8 output channels, 16 x 64 output tile.
#define OCB  8
#define TH   16
#define TW   64
#define XS_ROWS (TH + 2)              // 18
#define XS_COLS 68                    // 66 needed, padded (272 B/row, 16B-mult)
#define XS_ELEMS (XS_ROWS * XS_COLS)  // 1224
#define NLOAD 5                       // ceil(1224/256)
#define WSTRIDE 10                    // 9 taps padded to 10 (80 B, 16B aligned)

typedef unsigned long long u64;

// Packed f32x2 FMA: d.lo += a.lo*b.lo ; d.hi += a.hi*b.hi
__device__ __forceinline__ void fma2(u64& d, u64 a, u64 b) {
    asm("fma.rn.f32x2 %0, %1, %2, %0;" : "+l"(d) : "l"(a), "l"(b));
}

__device__ __forceinline__ u64 splat2(float v) {
    u64 bits = (u64)__float_as_uint(v);
    return bits | (bits << 32);
}

__global__ void __launch_bounds__(256, 2)
dynconv2d_kernel(const float* __restrict__ x,
                 const float* __restrict__ wgt,
                 const float* __restrict__ bias,
                 float* __restrict__ out) {
    // Splatted weights for this (b, oc-block), padded to 10 u64 per (oc,ci)
    // group so taps load as 4x LDS.128 + 1x LDS.64.
    __shared__ __align__(16) u64   ws[OCB * CI_ * WSTRIDE];   // 40,960 B
    __shared__ __align__(16) float xs[2][XS_ELEMS];           //  9,792 B

    const int tx  = threadIdx.x;            // 0..31 -> 2 output cols
    const int ty  = threadIdx.y;            // 0..7  -> 2 output rows
    const int tid = ty * 32 + tx;

    const int wt  = blockIdx.x;             // 0..1
    const int ht  = blockIdx.y;             // 0..7
    const int z   = blockIdx.z;             // 0..127
    const int b   = z >> 3;
    const int ocb = (z & 7) * OCB;
    const int h0  = ht * TH;
    const int w0  = wt * TW;

    // ---- Load + splat all weights for this block (4608 scalars) ----
    {
        const float* wg = wgt + (size_t)(b * CO_ + ocb) * CI_ * 9;
        #pragma unroll
        for (int k = 0; k < 18; k++) {
            int idx = tid + k * 256;           // 0..4607
            int g = idx / 9;
            int s = idx - g * 9;
            ws[g * WSTRIDE + s] = splat2(wg[idx]);
        }
    }

    // ---- Accumulators init with bias ----
    u64 acc[OCB][2];
    #pragma unroll
    for (int oc = 0; oc < OCB; oc++) {
        u64 bv = splat2(bias[b * CO_ + ocb + oc]);
        acc[oc][0] = bv;
        acc[oc][1] = bv;
    }

    // ---- Input-tile loader offsets (constant across ci) ----
    int gofs[NLOAD], sofs[NLOAD];
    bool lval[NLOAD];
    #pragma unroll
    for (int k = 0; k < NLOAD; k++) {
        int i = tid + k * 256;
        int r = i / XS_COLS;
        int c = i - r * XS_COLS;
        lval[k] = (i < XS_ELEMS);
        int gh = min(h0 + r, H_ - 1);   // clamped lanes feed only
        int gw = min(w0 + c, W_ - 1);   // predicated-off outputs
        gofs[k] = gh * W_ + gw;
        sofs[k] = i;
    }

    const float* xb = x + (size_t)b * CI_ * H_ * W_;

    // ---- Prologue: stage ci=0 into buffer 0 ----
    {
        float pf[NLOAD];
        #pragma unroll
        for (int k = 0; k < NLOAD; k++) if (lval[k]) pf[k] = xb[gofs[k]];
        #pragma unroll
        for (int k = 0; k < NLOAD; k++) if (lval[k]) xs[0][sofs[k]] = pf[k];
    }
    __syncthreads();

    // ---- Main loop over input channels (ping-pong, one barrier per ci) ----
    #pragma unroll 2
    for (int ci = 0; ci < CI_; ci++) {
        const float* cur = xs[ci & 1];
        float*       nxt = xs[(ci + 1) & 1];

        // Prefetch next channel's tile into registers.
        float pf[NLOAD];
        const bool more = (ci + 1 < CI_);
        if (more) {
            const float* xn = xb + (size_t)(ci + 1) * (H_ * W_);
            #pragma unroll
            for (int k = 0; k < NLOAD; k++) if (lval[k]) pf[k] = xn[gofs[k]];
        }

        // 4 input rows x 3 column-pairs; middle pair via 64-bit merge.
        u64 in[4][3];
        #pragma unroll
        for (int ir = 0; ir < 4; ir++) {
            const u64* rp = (const u64*)(cur + (ty * 2 + ir) * XS_COLS + 2 * tx);
            u64 pa = rp[0];
            u64 pb = rp[1];
            in[ir][0] = pa;
            in[ir][1] = (pa >> 32) | (pb << 32);
            in[ir][2] = pb;
        }

        // 8 oc x 2 rows x 9 taps = 144 packed FMAs / thread / ci.
        const u64* wrow = ws + ci * WSTRIDE;
        #pragma unroll
        for (int oc = 0; oc < OCB; oc++) {
            const u64* wp = wrow + oc * (CI_ * WSTRIDE);
            const ulonglong2* wp2 = (const ulonglong2*)wp;
            ulonglong2 w01 = wp2[0];
            ulonglong2 w23 = wp2[1];
            ulonglong2 w45 = wp2[2];
            ulonglong2 w67 = wp2[3];
            u64 w8 = wp[8];
            u64 wv[9] = {w01.x, w01.y, w23.x, w23.y,
                         w45.x, w45.y, w67.x, w67.y, w8};
            #pragma unroll
            for (int r = 0; r < 2; r++)
                #pragma unroll
                for (int kh = 0; kh < 3; kh++)
                    #pragma unroll
                    for (int kw = 0; kw < 3; kw++)
                        fma2(acc[oc][r], wv[kh * 3 + kw], in[r + kh][kw]);
        }

        // Commit prefetched tile into the other buffer.
        if (more) {
            #pragma unroll
            for (int k = 0; k < NLOAD; k++) if (lval[k]) nxt[sofs[k]] = pf[k];
        }
        __syncthreads();
    }

    // ---- Store (float2 per accumulator; bounds-predicated) ----
    const int ow = w0 + 2 * tx;
    if (ow < WO_) {   // ow even: valid => ow+1 valid too
        #pragma unroll
        for (int oc = 0; oc < OCB; oc++) {
            #pragma unroll
            for (int r = 0; r < 2; r++) {
                int oh = h0 + ty * 2 + r;
                if (oh < HO_) {
                    float2 v;
                    asm("mov.b64 {%0, %1}, %2;"
                        : "=f"(v.x), "=f"(v.y) : "l"(acc[oc][r]));
                    *(float2*)(out + ((size_t)(b * CO_ + ocb + oc) * HO_ + oh) * WO_ + ow) = v;
                }
            }
        }
    }
}

extern "C" void kernel_launch(void* const* d_in, const int* in_sizes, int n_in,
                              void* d_out, int out_size) {
    (void)in_sizes; (void)n_in; (void)out_size;
    const float* x    = (const float*)d_in[0];
    const float* wgt  = (const float*)d_in[1];
    const float* bias = (const float*)d_in[2];
    float* out        = (float*)d_out;

    dim3 block(32, 8, 1);
    dim3 grid(2,                         // W tiles (2 x 64 covers 126)
              (HO_ + TH - 1) / TH,       // 8 H tiles
              B_ * (CO_ / OCB));         // 128 (batch x oc-tiles)
    dynconv2d_kernel<<<grid, block>>>(x, wgt, bias, out);
}

// round 7
// speedup vs baseline: 1.2370x; 1.1359x over previous
#include <cuda_runtime.h>
#include <cuda_bf16.h>

// Shapes (fixed):
//   x:      (16, 64, 128, 128) f32
//   weight: (16, 64, 64, 3, 3) f32
//   bias:   (16, 64)           f32
//   out:    (16, 64, 126, 126) f32  (valid conv)
#define B_   16
#define CI_  64
#define CO_  64
#define H_   128
#define W_   128
#define HO_  126
#define WO_  126

// Block tiling: one batch, 8 output channels, 16 x 64 output tile.
// Input comes straight from gmem (L1/L2-resident), weights from smem.
#define OCB  8
#define TH   16
#define TW   64
#define WSTRIDE 10   // 9 taps padded to 10 u64 (80 B) -> 4x LDS.128 + 1x LDS.64

typedef unsigned long long u64;

// Packed f32x2 FMA: d.lo += a.lo*b.lo ; d.hi += a.hi*b.hi
__device__ __forceinline__ void fma2(u64& d, u64 a, u64 b) {
    asm("fma.rn.f32x2 %0, %1, %2, %0;" : "+l"(d) : "l"(a), "l"(b));
}

__device__ __forceinline__ u64 splat2(float v) {
    u64 bits = (u64)__float_as_uint(v);
    return bits | (bits << 32);
}

__global__ void __launch_bounds__(256, 2)
dynconv2d_kernel(const float* __restrict__ x,
                 const float* __restrict__ wgt,
                 const float* __restrict__ bias,
                 float* __restrict__ out) {
    // Splatted weights for this (b, oc-block). Loaded once; only barrier
    // in the whole kernel is right after this fill.
    __shared__ __align__(16) u64 ws[OCB * CI_ * WSTRIDE];   // 40,960 B

    const int tx  = threadIdx.x;            // 0..31 -> 2 output cols
    const int ty  = threadIdx.y;            // 0..7  -> 2 output rows
    const int tid = ty * 32 + tx;

    const int wt  = blockIdx.x;             // 0..1
    const int ht  = blockIdx.y;             // 0..7
    const int z   = blockIdx.z;             // 0..127
    const int b   = z >> 3;
    const int ocb = (z & 7) * OCB;
    const int h0  = ht * TH;
    const int w0  = wt * TW;

    // ---- Load + splat all weights for this block (4608 scalars) ----
    {
        const float* wg = wgt + (size_t)(b * CO_ + ocb) * CI_ * 9;
        #pragma unroll
        for (int k = 0; k < 18; k++) {
            int idx = tid + k * 256;           // 0..4607
            int g = idx / 9;
            int s = idx - g * 9;
            ws[g * WSTRIDE + s] = splat2(wg[idx]);
        }
    }

    // ---- Accumulators init with bias ----
    u64 acc[OCB][2];
    #pragma unroll
    for (int oc = 0; oc < OCB; oc++) {
        u64 bv = splat2(bias[b * CO_ + ocb + oc]);
        acc[oc][0] = bv;
        acc[oc][1] = bv;
    }

    // ---- Per-thread gmem offsets (constant across ci) ----
    // Thread needs input rows h0+2ty .. h0+2ty+3, cols w0+2tx .. w0+2tx+3.
    // Out-of-range rows/cols are clamped; the outputs that would consume
    // them are bounds-predicated at the store.
    const int col0 = w0 + 2 * tx;
    const int cpa  = min(col0,     W_ - 2);   // pa: cols cpa, cpa+1
    const int cpb  = min(col0 + 2, W_ - 2);   // pb: cols cpb, cpb+1
    int opa[4], opb[4];
    #pragma unroll
    for (int ir = 0; ir < 4; ir++) {
        int rr = min(h0 + 2 * ty + ir, H_ - 1);
        opa[ir] = rr * W_ + cpa;
        opb[ir] = rr * W_ + cpb;
    }

    const float* xb = x + (size_t)b * CI_ * H_ * W_;

    __syncthreads();   // ws visible; no further barriers

    // ---- Main loop over input channels (no smem staging, no barriers) ----
    #pragma unroll 2
    for (int ci = 0; ci < CI_; ci++) {
        const float* xp = xb + ci * (H_ * W_);

        // Front-batched coalesced LDG.64 (MLP = 8), L1/L2-resident.
        u64 pa[4], pb[4];
        #pragma unroll
        for (int ir = 0; ir < 4; ir++) pa[ir] = *(const u64*)(xp + opa[ir]);
        #pragma unroll
        for (int ir = 0; ir < 4; ir++) pb[ir] = *(const u64*)(xp + opb[ir]);

        // Middle pair (c1,c2) via 64-bit half-merge.
        u64 in[4][3];
        #pragma unroll
        for (int ir = 0; ir < 4; ir++) {
            in[ir][0] = pa[ir];
            in[ir][1] = (pa[ir] >> 32) | (pb[ir] << 32);
            in[ir][2] = pb[ir];
        }

        // 8 oc x 2 rows x 9 taps = 144 packed FMAs / thread / ci.
        const u64* wrow = ws + ci * WSTRIDE;
        #pragma unroll
        for (int oc = 0; oc < OCB; oc++) {
            const u64* wp = wrow + oc * (CI_ * WSTRIDE);
            const ulonglong2* wp2 = (const ulonglong2*)wp;
            ulonglong2 w01 = wp2[0];
            ulonglong2 w23 = wp2[1];
            ulonglong2 w45 = wp2[2];
            ulonglong2 w67 = wp2[3];
            u64 w8 = wp[8];
            u64 wv[9] = {w01.x, w01.y, w23.x, w23.y,
                         w45.x, w45.y, w67.x, w67.y, w8};
            #pragma unroll
            for (int r = 0; r < 2; r++)
                #pragma unroll
                for (int kh = 0; kh < 3; kh++)
                    #pragma unroll
                    for (int kw = 0; kw < 3; kw++)
                        fma2(acc[oc][r], wv[kh * 3 + kw], in[r + kh][kw]);
        }
    }

    // ---- Store (float2 per accumulator; bounds-predicated) ----
    const int ow = w0 + 2 * tx;
    if (ow < WO_) {   // ow even: valid => ow+1 valid too (ow <= 124)
        #pragma unroll
        for (int oc = 0; oc < OCB; oc++) {
            #pragma unroll
            for (int r = 0; r < 2; r++) {
                int oh = h0 + ty * 2 + r;
                if (oh < HO_) {
                    float2 v;
                    asm("mov.b64 {%0, %1}, %2;"
                        : "=f"(v.x), "=f"(v.y) : "l"(acc[oc][r]));
                    *(float2*)(out + ((size_t)(b * CO_ + ocb + oc) * HO_ + oh) * WO_ + ow) = v;
                }
            }
        }
    }
}

extern "C" void kernel_launch(void* const* d_in, const int* in_sizes, int n_in,
                              void* d_out, int out_size) {
    (void)in_sizes; (void)n_in; (void)out_size;
    const float* x    = (const float*)d_in[0];
    const float* wgt  = (const float*)d_in[1];
    const float* bias = (const float*)d_in[2];
    float* out        = (float*)d_out;

    dim3 block(32, 8, 1);
    dim3 grid(2,                         // W tiles (2 x 64 covers 126)
              (HO_ + TH - 1) / TH,       // 8 H tiles
              B_ * (CO_ / OCB));         // 128 (batch x oc-tiles)
    dynconv2d_kernel<<<grid, block>>>(x, wgt, bias, out);
}

// round 8
// speedup vs baseline: 1.2553x; 1.0149x over previous
#include <cuda_runtime.h>
#include <cuda_bf16.h>

// Shapes (fixed):
//   x:      (16, 64, 128, 128) f32
//   weight: (16, 64, 64, 3, 3) f32
//   bias:   (16, 64)           f32
//   out:    (16, 64, 126, 126) f32  (valid conv)
#define B_   16
#define CI_  64
#define CO_  64
#define H_   128
#define W_   128
#define HO_  126
#define WO_  126
#define HW_  (H_ * W_)

// Block tiling: one batch, 8 output channels, 16 x 64 output tile.
// Boundary tiles are SHIFTED (h0=110, w0=62) instead of clamped:
// overlapping outputs are recomputed identically and double-stored,
// so there are no clamps and no store predicates anywhere.
#define OCB  8
#define WSTRIDE 10   // 9 taps padded to 10 u64 (80 B): 4x LDS.128 + 1x LDS.64

typedef unsigned long long u64;

// Packed f32x2 FMA: d.lo += a.lo*b.lo ; d.hi += a.hi*b.hi
__device__ __forceinline__ void fma2(u64& d, u64 a, u64 b) {
    asm("fma.rn.f32x2 %0, %1, %2, %0;" : "+l"(d) : "l"(a), "l"(b));
}

__device__ __forceinline__ u64 splat2(float v) {
    u64 bits = (u64)__float_as_uint(v);
    return bits | (bits << 32);
}

// Pack two 32-bit lanes into one 64-bit operand (register-pair select).
__device__ __forceinline__ u64 pack2(unsigned lo, unsigned hi) {
    u64 r;
    asm("mov.b64 %0, {%1, %2};" : "=l"(r) : "r"(lo), "r"(hi));
    return r;
}

__global__ void __launch_bounds__(256, 2)
dynconv2d_kernel(const float* __restrict__ x,
                 const float* __restrict__ wgt,
                 const float* __restrict__ bias,
                 float* __restrict__ out) {
    // Splatted weights for this (b, oc-block); only barrier in the kernel.
    __shared__ __align__(16) u64 ws[OCB * CI_ * WSTRIDE];   // 40,960 B

    const int tx  = threadIdx.x;            // 0..31 -> 2 output cols
    const int ty  = threadIdx.y;            // 0..7  -> 2 output rows
    const int tid = ty * 32 + tx;

    const int wt  = blockIdx.x;             // 0..1
    const int ht  = blockIdx.y;             // 0..7
    const int z   = blockIdx.z;             // 0..127
    const int b   = z >> 3;
    const int ocb = (z & 7) * OCB;
    const int h0  = (ht == 7) ? (HO_ - 16) : ht * 16;   // 110 on last tile
    const int w0  = (wt == 1) ? (WO_ - 64) : 0;         // 62 on last tile

    // ---- Load + splat all weights for this block (4608 scalars) ----
    {
        const float* wg = wgt + (size_t)(b * CO_ + ocb) * CI_ * 9;
        #pragma unroll
        for (int k = 0; k < 18; k++) {
            int idx = tid + k * 256;           // 0..4607
            int g = idx / 9;
            int s = idx - g * 9;
            ws[g * WSTRIDE + s] = splat2(wg[idx]);
        }
    }

    // ---- Accumulators init with bias ----
    u64 acc[OCB][2];
    #pragma unroll
    for (int oc = 0; oc < OCB; oc++) {
        u64 bv = splat2(bias[b * CO_ + ocb + oc]);
        acc[oc][0] = bv;
        acc[oc][1] = bv;
    }

    // ---- Per-thread input base pointer; ALL row/col offsets are constants ----
    // Thread reads rows h0+2ty .. h0+2ty+3 (all <= 127 by tile shift),
    // cols w0+2tx .. w0+2tx+3 (all <= 127).
    const unsigned* xp = (const unsigned*)
        (x + (size_t)b * CI_ * HW_ + (h0 + 2 * ty) * W_ + (w0 + 2 * tx));

    __syncthreads();   // ws visible; no further barriers

    // ---- Prologue: stage ci=0 loads ----
    uint2 pa[4], pb[4];
    #pragma unroll
    for (int ir = 0; ir < 4; ir++) {
        pa[ir] = *(const uint2*)(xp + ir * W_);
        pb[ir] = *(const uint2*)(xp + ir * W_ + 2);
    }

    // ---- Main loop: build pairs -> prefetch next ci -> 144 FMA2 ----
    #pragma unroll 2
    for (int ci = 0; ci < CI_; ci++) {
        // Column pairs (c0,c1),(c1,c2),(c2,c3) per row from staged loads.
        u64 in[4][3];
        #pragma unroll
        for (int ir = 0; ir < 4; ir++) {
            in[ir][0] = pack2(pa[ir].x, pa[ir].y);
            in[ir][1] = pack2(pa[ir].y, pb[ir].x);
            in[ir][2] = pack2(pb[ir].x, pb[ir].y);
        }

        // Prefetch next channel (immediate-offset LDGs off one bumped base).
        xp += HW_;
        if (ci + 1 < CI_) {
            #pragma unroll
            for (int ir = 0; ir < 4; ir++) {
                pa[ir] = *(const uint2*)(xp + ir * W_);
                pb[ir] = *(const uint2*)(xp + ir * W_ + 2);
            }
        }

        // 8 oc x 2 rows x 9 taps, weights streamed 2 taps at a time.
        const u64* wrow = ws + ci * WSTRIDE;
        #pragma unroll
        for (int oc = 0; oc < OCB; oc++) {
            const u64* wp = wrow + oc * (CI_ * WSTRIDE);
            const ulonglong2* wp2 = (const ulonglong2*)wp;
            ulonglong2 wA = wp2[0];                 // taps 0,1
            ulonglong2 wB = wp2[1];                 // taps 2,3
            fma2(acc[oc][0], wA.x, in[0][0]); fma2(acc[oc][1], wA.x, in[1][0]);
            fma2(acc[oc][0], wA.y, in[0][1]); fma2(acc[oc][1], wA.y, in[1][1]);
            fma2(acc[oc][0], wB.x, in[0][2]); fma2(acc[oc][1], wB.x, in[1][2]);
            fma2(acc[oc][0], wB.y, in[1][0]); fma2(acc[oc][1], wB.y, in[2][0]);
            ulonglong2 wC = wp2[2];                 // taps 4,5
            ulonglong2 wD = wp2[3];                 // taps 6,7
            fma2(acc[oc][0], wC.x, in[1][1]); fma2(acc[oc][1], wC.x, in[2][1]);
            fma2(acc[oc][0], wC.y, in[1][2]); fma2(acc[oc][1], wC.y, in[2][2]);
            fma2(acc[oc][0], wD.x, in[2][0]); fma2(acc[oc][1], wD.x, in[3][0]);
            fma2(acc[oc][0], wD.y, in[2][1]); fma2(acc[oc][1], wD.y, in[3][1]);
            u64 w8 = wp[8];                         // tap 8
            fma2(acc[oc][0], w8, in[2][2]); fma2(acc[oc][1], w8, in[3][2]);
        }
    }

    // ---- Store: every output in the (shifted) tile is valid ----
    const int ow = w0 + 2 * tx;
    #pragma unroll
    for (int oc = 0; oc < OCB; oc++) {
        #pragma unroll
        for (int r = 0; r < 2; r++) {
            int oh = h0 + 2 * ty + r;
            float2 v;
            asm("mov.b64 {%0, %1}, %2;" : "=f"(v.x), "=f"(v.y) : "l"(acc[oc][r]));
            *(float2*)(out + ((size_t)(b * CO_ + ocb + oc) * HO_ + oh) * WO_ + ow) = v;
        }
    }
}

extern "C" void kernel_launch(void* const* d_in, const int* in_sizes, int n_in,
                              void* d_out, int out_size) {
    (void)in_sizes; (void)n_in; (void)out_size;
    const float* x    = (const float*)d_in[0];
    const float* wgt  = (const float*)d_in[1];
    const float* bias = (const float*)d_in[2];
    float* out        = (float*)d_out;

    dim3 block(32, 8, 1);
    dim3 grid(2,                     // W tiles: w0 in {0, 62}
              8,                     // H tiles: h0 in {0,16,...,96,110}
              B_ * (CO_ / OCB));     // 128 (batch x oc-tiles)
    dynconv2d_kernel<<<grid, block>>>(x, wgt, bias, out);
}

// round 9
// speedup vs baseline: 1.2569x; 1.0012x over previous
#include <cuda_runtime.h>
#include <cuda_bf16.h>

// Shapes (fixed):
//   x:      (16, 64, 128, 128) f32
//   weight: (16, 64, 64, 3, 3) f32
//   bias:   (16, 64)           f32
//   out:    (16, 64, 126, 126) f32  (valid conv)
#define B_   16
#define CI_  64
#define CO_  64
#define H_   128
#define W_   128
#define HO_  126
#define WO_  126
#define HW_  (H_ * W_)

// Block tiling: one batch, 8 output channels, 16 x 64 output tile.
// Boundary tiles are SHIFTED (h0=110, w0=62) instead of clamped:
// overlapping outputs are recomputed identically and double-stored,
// so there are no clamps and no store predicates anywhere.
#define OCB  8
#define WSTRIDE 10   // 9 taps padded to 10 u64 (80 B): 4x LDS.128 + 1x LDS.64

typedef unsigned long long u64;

// Packed f32x2 FMA: d.lo += a.lo*b.lo ; d.hi += a.hi*b.hi
__device__ __forceinline__ void fma2(u64& d, u64 a, u64 b) {
    asm("fma.rn.f32x2 %0, %1, %2, %0;" : "+l"(d) : "l"(a), "l"(b));
}

__device__ __forceinline__ u64 splat2(float v) {
    u64 bits = (u64)__float_as_uint(v);
    return bits | (bits << 32);
}

// Pack two 32-bit lanes into one 64-bit operand (register-pair select).
__device__ __forceinline__ u64 pack2(unsigned lo, unsigned hi) {
    u64 r;
    asm("mov.b64 %0, {%1, %2};" : "=l"(r) : "r"(lo), "r"(hi));
    return r;
}

__global__ void __launch_bounds__(256, 2)
dynconv2d_kernel(const float* __restrict__ x,
                 const float* __restrict__ wgt,
                 const float* __restrict__ bias,
                 float* __restrict__ out) {
    // Splatted weights for this (b, oc-block); only barrier in the kernel.
    __shared__ __align__(16) u64 ws[OCB * CI_ * WSTRIDE];   // 40,960 B

    const int tx  = threadIdx.x;            // 0..31 -> 2 output cols
    const int ty  = threadIdx.y;            // 0..7  -> 2 output rows
    const int tid = ty * 32 + tx;

    const int wt  = blockIdx.x;             // 0..1
    const int ht  = blockIdx.y;             // 0..7
    const int z   = blockIdx.z;             // 0..127
    const int b   = z >> 3;
    const int ocb = (z & 7) * OCB;
    const int h0  = (ht == 7) ? (HO_ - 16) : ht * 16;   // 110 on last tile
    const int w0  = (wt == 1) ? (WO_ - 64) : 0;         // 62 on last tile

    // ---- Load + splat all weights for this block (4608 scalars) ----
    {
        const float* wg = wgt + (size_t)(b * CO_ + ocb) * CI_ * 9;
        #pragma unroll
        for (int k = 0; k < 18; k++) {
            int idx = tid + k * 256;           // 0..4607
            int g = idx / 9;
            int s = idx - g * 9;
            ws[g * WSTRIDE + s] = splat2(wg[idx]);
        }
    }

    // ---- Accumulators init with bias ----
    u64 acc[OCB][2];
    #pragma unroll
    for (int oc = 0; oc < OCB; oc++) {
        u64 bv = splat2(bias[b * CO_ + ocb + oc]);
        acc[oc][0] = bv;
        acc[oc][1] = bv;
    }

    // ---- Per-thread input base pointer; ALL row/col offsets are constants ----
    // Thread reads rows h0+2ty .. h0+2ty+3 (all <= 127 by tile shift),
    // cols w0+2tx .. w0+2tx+3 (all <= 127).
    const unsigned* xp = (const unsigned*)
        (x + (size_t)b * CI_ * HW_ + (h0 + 2 * ty) * W_ + (w0 + 2 * tx));

    __syncthreads();   // ws visible; no further barriers

    // ---- Prologue: stage ci=0 loads ----
    uint2 pa[4], pb[4];
    #pragma unroll
    for (int ir = 0; ir < 4; ir++) {
        pa[ir] = *(const uint2*)(xp + ir * W_);
        pb[ir] = *(const uint2*)(xp + ir * W_ + 2);
    }

    // ---- Main loop: build pairs -> prefetch next ci -> 144 FMA2 ----
    #pragma unroll 2
    for (int ci = 0; ci < CI_; ci++) {
        // Column pairs (c0,c1),(c1,c2),(c2,c3) per row from staged loads.
        u64 in[4][3];
        #pragma unroll
        for (int ir = 0; ir < 4; ir++) {
            in[ir][0] = pack2(pa[ir].x, pa[ir].y);
            in[ir][1] = pack2(pa[ir].y, pb[ir].x);
            in[ir][2] = pack2(pb[ir].x, pb[ir].y);
        }

        // Prefetch next channel (immediate-offset LDGs off one bumped base).
        xp += HW_;
        if (ci + 1 < CI_) {
            #pragma unroll
            for (int ir = 0; ir < 4; ir++) {
                pa[ir] = *(const uint2*)(xp + ir * W_);
                pb[ir] = *(const uint2*)(xp + ir * W_ + 2);
            }
        }

        // 8 oc x 2 rows x 9 taps, weights streamed 2 taps at a time.
        const u64* wrow = ws + ci * WSTRIDE;
        #pragma unroll
        for (int oc = 0; oc < OCB; oc++) {
            const u64* wp = wrow + oc * (CI_ * WSTRIDE);
            const ulonglong2* wp2 = (const ulonglong2*)wp;
            ulonglong2 wA = wp2[0];                 // taps 0,1
            ulonglong2 wB = wp2[1];                 // taps 2,3
            fma2(acc[oc][0], wA.x, in[0][0]); fma2(acc[oc][1], wA.x, in[1][0]);
            fma2(acc[oc][0], wA.y, in[0][1]); fma2(acc[oc][1], wA.y, in[1][1]);
            fma2(acc[oc][0], wB.x, in[0][2]); fma2(acc[oc][1], wB.x, in[1][2]);
            fma2(acc[oc][0], wB.y, in[1][0]); fma2(acc[oc][1], wB.y, in[2][0]);
            ulonglong2 wC = wp2[2];                 // taps 4,5
            ulonglong2 wD = wp2[3];                 // taps 6,7
            fma2(acc[oc][0], wC.x, in[1][1]); fma2(acc[oc][1], wC.x, in[2][1]);
            fma2(acc[oc][0], wC.y, in[1][2]); fma2(acc[oc][1], wC.y, in[2][2]);
            fma2(acc[oc][0], wD.x, in[2][0]); fma2(acc[oc][1], wD.x, in[3][0]);
            fma2(acc[oc][0], wD.y, in[2][1]); fma2(acc[oc][1], wD.y, in[3][1]);
            u64 w8 = wp[8];                         // tap 8
            fma2(acc[oc][0], w8, in[2][2]); fma2(acc[oc][1], w8, in[3][2]);
        }
    }

    // ---- Store: every output in the (shifted) tile is valid ----
    const int ow = w0 + 2 * tx;
    #pragma unroll
    for (int oc = 0; oc < OCB; oc++) {
        #pragma unroll
        for (int r = 0; r < 2; r++) {
            int oh = h0 + 2 * ty + r;
            float2 v;
            asm("mov.b64 {%0, %1}, %2;" : "=f"(v.x), "=f"(v.y) : "l"(acc[oc][r]));
            *(float2*)(out + ((size_t)(b * CO_ + ocb + oc) * HO_ + oh) * WO_ + ow) = v;
        }
    }
}

extern "C" void kernel_launch(void* const* d_in, const int* in_sizes, int n_in,
                              void* d_out, int out_size) {
    (void)in_sizes; (void)n_in; (void)out_size;
    const float* x    = (const float*)d_in[0];
    const float* wgt  = (const float*)d_in[1];
    const float* bias = (const float*)d_in[2];
    float* out        = (float*)d_out;

    dim3 block(32, 8, 1);
    dim3 grid(2,                     // W tiles: w0 in {0, 62}
              8,                     // H tiles: h0 in {0,16,...,96,110}
              B_ * (CO_ / OCB));     // 128 (batch x oc-tiles)
    dynconv2d_kernel<<<grid, block>>>(x, wgt, bias, out);
}

// round 11
// speedup vs baseline: 1.6536x; 1.3157x over previous
#include <cuda_runtime.h>
#include <cuda_bf16.h>
#include <cstdint>

#define B_   16
#define CI_  64
#define CO_  64
#define H_   128
#define W_   128
#define HO_  126
#define WO_  126
#define TAPS 9

// ---- device scratch (static; no allocation APIs) ----
__device__ __nv_bfloat16 g_xth[(size_t)B_ * H_ * W_ * CI_];
__device__ __nv_bfloat16 g_xtl[(size_t)B_ * H_ * W_ * CI_];
__device__ __nv_bfloat16 g_wth[(size_t)B_ * TAPS * CO_ * CI_];
__device__ __nv_bfloat16 g_wtl[(size_t)B_ * TAPS * CO_ * CI_];

// ---- smem layout (dynamic) ----
// A: [half][row 3][w 136][ci 64] bf16, 128B per w, XOR-swizzled 16B chunks
#define A_ROW_BYTES   17408            // 136 * 128
#define A_HALF_BYTES  52224            // 3 * 17408
#define SB_OFF        104448           // 2 * A_HALF_BYTES
#define B_BUF_BYTES   16384            // half(2) * 64co * 128B
#define SMEM_BYTES    137216           // SB_OFF + 2 * B_BUF_BYTES

// ---- baseline-target PTX helpers (no sm_103a features) ----
__device__ __forceinline__ uint32_t smem_u32(const void* p) {
    uint32_t a;
    asm("{ .reg .u64 t; cvta.to.shared.u64 t, %1; cvt.u32.u64 %0, t; }" : "=r"(a) : "l"(p));
    return a;
}
#define CPA16(dst, src) \
    asm volatile("cp.async.cg.shared.global [%0], [%1], 16;" :: "r"(dst), "l"(src))
#define CPA_COMMIT() asm volatile("cp.async.commit_group;" ::: "memory")
#define CPA_WAIT0()  asm volatile("cp.async.wait_group 0;" ::: "memory")

__device__ __forceinline__ void ldsm4(uint32_t addr, uint32_t r[4]) {
    asm volatile("ldmatrix.sync.aligned.m8n8.x4.shared.b16 {%0,%1,%2,%3}, [%4];"
        : "=r"(r[0]), "=r"(r[1]), "=r"(r[2]), "=r"(r[3]) : "r"(addr));
}
__device__ __forceinline__ void mma16816(float d[4], const uint32_t a[4],
                                         uint32_t b0, uint32_t b1) {
    asm volatile("mma.sync.aligned.m16n8k16.row.col.f32.bf16.bf16.f32 "
        "{%0,%1,%2,%3},{%4,%5,%6,%7},{%8,%9},{%0,%1,%2,%3};"
        : "+f"(d[0]), "+f"(d[1]), "+f"(d[2]), "+f"(d[3])
        : "r"(a[0]), "r"(a[1]), "r"(a[2]), "r"(a[3]), "r"(b0), "r"(b1));
}

// ---- prepass 1: x (B,CI,H,W) f32 -> split bf16 [b*H+h][w][ci] ----
__global__ void prepass_x(const float* __restrict__ x) {
    __shared__ float tile[32][33];
    int wt0 = (blockIdx.x >> 1) * 32, ct0 = (blockIdx.x & 1) * 32;
    int h = blockIdx.y, b = blockIdx.z;
    tile[threadIdx.y][threadIdx.x] =
        x[(((size_t)b * CI_ + ct0 + threadIdx.y) * H_ + h) * W_ + wt0 + threadIdx.x];
    __syncthreads();
    int t = threadIdx.y * 32 + threadIdx.x;
    int half = t >> 9, r = t & 511, w = r >> 4, cp = r & 15;
    float a0 = tile[2 * cp][w], a1 = tile[2 * cp + 1][w];
    __nv_bfloat16 h0 = __float2bfloat16(a0), h1 = __float2bfloat16(a1);
    __nv_bfloat162 v = half
        ? __nv_bfloat162(__float2bfloat16(a0 - __bfloat162float(h0)),
                         __float2bfloat16(a1 - __bfloat162float(h1)))
        : __nv_bfloat162(h0, h1);
    __nv_bfloat16* dst = half ? g_xtl : g_xth;
    *(__nv_bfloat162*)(dst + ((size_t)(b * H_ + h) * W_ + wt0 + w) * CI_ + ct0 + 2 * cp) = v;
}

// ---- prepass 2: weight (B,CO,CI,3,3) f32 -> split bf16 [b*9+t][co][ci] ----
__global__ void prepass_w(const float* __restrict__ wgt) {
    int idx = blockIdx.x * 256 + threadIdx.x;       // (b,co,ci)
    int ci = idx & 63, co = (idx >> 6) & 63, b = idx >> 12;
    const float* wp = wgt + (size_t)idx * TAPS;
    #pragma unroll
    for (int t = 0; t < TAPS; t++) {
        float v = wp[t];
        __nv_bfloat16 hh = __float2bfloat16(v);
        size_t o = ((size_t)(b * TAPS + t) * CO_ + co) * CI_ + ci;
        g_wth[o] = hh;
        g_wtl[o] = __float2bfloat16(v - __bfloat162float(hh));
    }
}

// ---- B-tap loader: g_wt{h,l}[b*9+t][co][ci] -> swizzled smem buf ----
__device__ __forceinline__ void load_b_tap(uint32_t sB, int tid, int b, int t, int buf) {
    #pragma unroll
    for (int k = 0; k < 4; k++) {
        int i = tid + k * 256;                 // 0..1023
        int half = i >> 9, rem = i & 511;
        int co = rem >> 3, c = rem & 7;
        uint32_t dst = sB + buf * B_BUF_BYTES + half * 8192 +
                       co * 128 + (((c ^ (co & 7)) << 4));
        const __nv_bfloat16* g = half ? g_wtl : g_wth;
        const char* src = (const char*)(g + (((size_t)(b * TAPS + t)) * CO_ + co) * CI_ + c * 8);
        CPA16(dst, src);
    }
}

// ---- main: per (b, oh), 9 tap-GEMMs via mma.sync bf16 3-pass split ----
__global__ void __launch_bounds__(256)
conv_hmma(const float* __restrict__ bias, float* __restrict__ out) {
    extern __shared__ char sm[];
    const int tid  = threadIdx.x;
    const int lane = tid & 31, wid = tid >> 5;
    const int b  = blockIdx.x / HO_;
    const int oh = blockIdx.x - b * HO_;
    const int pbase  = (wid >> 1) * 32;     // 4 warps along p (128)
    const int cobase = (wid & 1) * 32;      // 2 warps along co (64)

    const uint32_t sA = smem_u32(sm);
    const uint32_t sB = sA + SB_OFF;

    // zero-fill the w=128..135 pad (readable by padded p rows)
    if (tid < 384) {
        int half = tid / 192, rem = tid - half * 192;
        int row = rem >> 6, rem2 = rem & 63;
        int w = 128 + (rem2 >> 3), c = rem2 & 7;
        *(uint4*)(sm + half * A_HALF_BYTES + row * A_ROW_BYTES +
                  w * 128 + ((c ^ (w & 7)) << 4)) = make_uint4(0, 0, 0, 0);
    }

    // A: stage 3 input rows (both halves) via cp.async, swizzled
    #pragma unroll
    for (int k = 0; k < 24; k++) {
        int i = tid + k * 256;                 // 0..6143
        int half = i / 3072, rem = i - half * 3072;
        int row = rem >> 10, rem2 = rem & 1023;
        int w = rem2 >> 3, c = rem2 & 7;
        uint32_t dst = sA + half * A_HALF_BYTES + row * A_ROW_BYTES +
                       w * 128 + ((c ^ (w & 7)) << 4);
        const __nv_bfloat16* g = half ? g_xtl : g_xth;
        const char* src = (const char*)(g + (((size_t)(b * H_ + oh + row)) * W_ + w) * CI_ + c * 8);
        CPA16(dst, src);
    }
    load_b_tap(sB, tid, b, 0, 0);
    CPA_COMMIT();
    CPA_WAIT0();
    __syncthreads();

    // lane constants for ldmatrix addressing
    const int dw = lane & 15, hi = lane >> 4;
    const int bco = (lane & 7) + ((lane >> 3) & 1) * 8;
    const int co0 = cobase + bco,        co1 = co0 + 16;
    const int boff0 = co0 * 128, b7_0 = co0 & 7;
    const int boff1 = co1 * 128, b7_1 = co1 & 7;
    const int aw = pbase + dw;

    float acc[2][4][4];
    #pragma unroll
    for (int m = 0; m < 2; m++)
        #pragma unroll
        for (int n = 0; n < 4; n++)
            #pragma unroll
            for (int e = 0; e < 4; e++) acc[m][n][e] = 0.f;

    int kh = 0, kw = 0;
    for (int t = 0; t < TAPS; t++) {
        if (t < 8) { load_b_tap(sB, tid, b, t + 1, (t + 1) & 1); CPA_COMMIT(); }

        const uint32_t arow = sA + kh * A_ROW_BYTES;
        const int w0 = aw + kw, w1 = w0 + 16;
        const uint32_t a0b = arow + w0 * 128, a1b = arow + w1 * 128;
        const int w07 = w0 & 7, w17 = w1 & 7;
        const uint32_t bb = sB + (t & 1) * B_BUF_BYTES;

        #pragma unroll
        for (int kk = 0; kk < 4; kk++) {
            const int kc = kk * 2 + hi;
            uint32_t ah0[4], ah1[4], al0[4], al1[4];
            uint32_t aH0 = a0b + ((kc ^ w07) << 4);
            uint32_t aH1 = a1b + ((kc ^ w17) << 4);
            ldsm4(aH0, ah0);                ldsm4(aH1, ah1);
            ldsm4(aH0 + A_HALF_BYTES, al0); ldsm4(aH1 + A_HALF_BYTES, al1);

            uint32_t bh0[4], bh1[4], bl0[4], bl1[4];
            uint32_t bB0 = bb + boff0 + ((kc ^ b7_0) << 4);
            uint32_t bB1 = bb + boff1 + ((kc ^ b7_1) << 4);
            ldsm4(bB0, bh0);        ldsm4(bB1, bh1);
            ldsm4(bB0 + 8192, bl0); ldsm4(bB1 + 8192, bl1);

            #pragma unroll
            for (int n = 0; n < 4; n++) {
                const uint32_t* Bh = (n < 2) ? bh0 : bh1;
                const uint32_t* Bl = (n < 2) ? bl0 : bl1;
                const int s = n & 1;
                mma16816(acc[0][n], ah0, Bh[s], Bh[s + 2]);   // Ah*Bh
                mma16816(acc[1][n], ah1, Bh[s], Bh[s + 2]);
                mma16816(acc[0][n], al0, Bh[s], Bh[s + 2]);   // Al*Bh
                mma16816(acc[1][n], al1, Bh[s], Bh[s + 2]);
                mma16816(acc[0][n], ah0, Bl[s], Bl[s + 2]);   // Ah*Bl
                mma16816(acc[1][n], ah1, Bl[s], Bl[s + 2]);
            }
        }
        if (t < 8) CPA_WAIT0();
        __syncthreads();
        if (++kw == 3) { kw = 0; ++kh; }
    }

    // epilogue: regs -> smem [co][p] f32 (reuse A region), then coalesced out
    float* smf = (float*)sm;
    const int rowq = lane >> 2, colp = 2 * (lane & 3);
    #pragma unroll
    for (int m = 0; m < 2; m++)
        #pragma unroll
        for (int n = 0; n < 4; n++) {
            int p0 = pbase + m * 16 + rowq;
            int c0 = cobase + n * 8 + colp;
            smf[c0 * 128 + p0]           = acc[m][n][0];
            smf[(c0 + 1) * 128 + p0]     = acc[m][n][1];
            smf[c0 * 128 + p0 + 8]       = acc[m][n][2];
            smf[(c0 + 1) * 128 + p0 + 8] = acc[m][n][3];
        }
    __syncthreads();

    const int co = tid >> 2, q = tid & 3;
    const float bv = bias[b * CO_ + co];
    float* op = out + ((size_t)(b * CO_ + co) * HO_ + oh) * WO_;
    #pragma unroll
    for (int i = 0; i < 32; i++) {
        int p = q * 32 + i;
        if (p < WO_) op[p] = smf[co * 128 + p] + bv;
    }
}

extern "C" void kernel_launch(void* const* d_in, const int* in_sizes, int n_in,
                              void* d_out, int out_size) {
    (void)in_sizes; (void)n_in; (void)out_size;
    const float* x    = (const float*)d_in[0];
    const float* wgt  = (const float*)d_in[1];
    const float* bias = (const float*)d_in[2];
    float* out        = (float*)d_out;

    static bool attr_set = false;
    if (!attr_set) {
        cudaFuncSetAttribute(conv_hmma, cudaFuncAttributeMaxDynamicSharedMemorySize,
                             SMEM_BYTES);
        attr_set = true;
    }

    prepass_x<<<dim3(8, H_, B_), dim3(32, 32)>>>(x);
    prepass_w<<<256, 256>>>(wgt);
    conv_hmma<<<B_ * HO_, 256, SMEM_BYTES>>>(bias, out);
}

// round 12
// speedup vs baseline: 2.0520x; 1.2409x over previous
#include <cuda_runtime.h>
#include <cuda_bf16.h>
#include <cstdint>

#define B_   16
#define CI_  64
#define CO_  64
#define H_   128
#define W_   128
#define HO_  126
#define WO_  126
#define TAPS 9

// ---- device scratch (static; no allocation APIs) ----
__device__ __nv_bfloat16 g_xth[(size_t)B_ * H_ * W_ * CI_];
__device__ __nv_bfloat16 g_xtl[(size_t)B_ * H_ * W_ * CI_];
__device__ __nv_bfloat16 g_wth[(size_t)B_ * TAPS * CO_ * CI_];
__device__ __nv_bfloat16 g_wtl[(size_t)B_ * TAPS * CO_ * CI_];

// ---- smem layout (dynamic), kTile = 2 output rows per CTA ----
// A: [half 2][row 4][w 130][ci 64] bf16, 128B per w, XOR-swizzled 16B chunks
#define A_ROWS        4
#define A_PAD_W       130              // max addressed w-row = 129
#define A_ROW_BYTES   (A_PAD_W * 128)  // 16640
#define A_HALF_BYTES  (A_ROWS * A_ROW_BYTES)   // 66560
#define SB_OFF        (2 * A_HALF_BYTES)       // 133120
#define B_BUF_BYTES   16384            // half(2) * 64co * 128B
#define SMEM_BYTES    (SB_OFF + 2 * B_BUF_BYTES)   // 165888

// ---- baseline-target PTX helpers ----
__device__ __forceinline__ uint32_t smem_u32(const void* p) {
    uint32_t a;
    asm("{ .reg .u64 t; cvta.to.shared.u64 t, %1; cvt.u32.u64 %0, t; }" : "=r"(a) : "l"(p));
    return a;
}
#define CPA16(dst, src) \
    asm volatile("cp.async.cg.shared.global [%0], [%1], 16;" :: "r"(dst), "l"(src))
#define CPA_COMMIT() asm volatile("cp.async.commit_group;" ::: "memory")
#define CPA_WAIT0()  asm volatile("cp.async.wait_group 0;" ::: "memory")

__device__ __forceinline__ void ldsm4(uint32_t addr, uint32_t r[4]) {
    asm volatile("ldmatrix.sync.aligned.m8n8.x4.shared.b16 {%0,%1,%2,%3}, [%4];"
        : "=r"(r[0]), "=r"(r[1]), "=r"(r[2]), "=r"(r[3]) : "r"(addr));
}
__device__ __forceinline__ void mma16816(float d[4], const uint32_t a[4],
                                         uint32_t b0, uint32_t b1) {
    asm volatile("mma.sync.aligned.m16n8k16.row.col.f32.bf16.bf16.f32 "
        "{%0,%1,%2,%3},{%4,%5,%6,%7},{%8,%9},{%0,%1,%2,%3};"
        : "+f"(d[0]), "+f"(d[1]), "+f"(d[2]), "+f"(d[3])
        : "r"(a[0]), "r"(a[1]), "r"(a[2]), "r"(a[3]), "r"(b0), "r"(b1));
}

// ---- prepass 1: x (B,CI,H,W) f32 -> split bf16 [b*H+h][w][ci] ----
// One 256-thread block per (b,h): float4 reads, contiguous 16B dual writes.
__global__ void __launch_bounds__(256) prepass_x(const float* __restrict__ x) {
    __shared__ float tile[64 * 129];
    const int t = threadIdx.x;
    const int h = blockIdx.x & 127, b = blockIdx.x >> 7;
    const float* xb = x + ((size_t)b * CI_ * H_ + h) * W_;

    #pragma unroll
    for (int j = 0; j < 8; j++) {
        int idx = j * 256 + t;                  // 0..2047
        int ci = idx >> 5, w4 = (idx & 31) << 2;
        const float4 v = *(const float4*)(xb + (size_t)ci * (H_ * W_) + w4);
        float* dst = tile + ci * 129 + w4;
        dst[0] = v.x; dst[1] = v.y; dst[2] = v.z; dst[3] = v.w;
    }
    __syncthreads();

    const int ci0 = (t & 7) * 8;
    #pragma unroll
    for (int i = 0; i < 4; i++) {
        int w = i * 32 + (t >> 3);
        __nv_bfloat16 hi8[8], lo8[8];
        #pragma unroll
        for (int c = 0; c < 8; c++) {
            float v = tile[(ci0 + c) * 129 + w];
            __nv_bfloat16 hh = __float2bfloat16(v);
            hi8[c] = hh;
            lo8[c] = __float2bfloat16(v - __bfloat162float(hh));
        }
        size_t o = ((size_t)(b * H_ + h) * W_ + w) * CI_ + ci0;
        *(uint4*)(g_xth + o) = *(uint4*)hi8;
        *(uint4*)(g_xtl + o) = *(uint4*)lo8;
    }
}

// ---- prepass 2: weight (B,CO,CI,3,3) f32 -> split bf16 [b*9+t][co][ci] ----
__global__ void prepass_w(const float* __restrict__ wgt) {
    int idx = blockIdx.x * 256 + threadIdx.x;       // (b,co,ci)
    int ci = idx & 63, co = (idx >> 6) & 63, b = idx >> 12;
    const float* wp = wgt + (size_t)idx * TAPS;
    #pragma unroll
    for (int t = 0; t < TAPS; t++) {
        float v = wp[t];
        __nv_bfloat16 hh = __float2bfloat16(v);
        size_t o = ((size_t)(b * TAPS + t) * CO_ + co) * CI_ + ci;
        g_wth[o] = hh;
        g_wtl[o] = __float2bfloat16(v - __bfloat162float(hh));
    }
}

// ---- B-tap loader: g_wt{h,l}[b*9+t][co][ci] -> swizzled smem buf ----
__device__ __forceinline__ void load_b_tap(uint32_t sB, int tid, int b, int t, int buf) {
    #pragma unroll
    for (int k = 0; k < 4; k++) {
        int i = tid + k * 256;                 // 0..1023
        int half = i >> 9, rem = i & 511;
        int co = rem >> 3, c = rem & 7;
        uint32_t dst = sB + buf * B_BUF_BYTES + half * 8192 +
                       co * 128 + (((c ^ (co & 7)) << 4));
        const __nv_bfloat16* g = half ? g_wtl : g_wth;
        const char* src = (const char*)(g + (((size_t)(b * TAPS + t)) * CO_ + co) * CI_ + c * 8);
        CPA16(dst, src);
    }
}

// ---- main: per (b, 2x oh), 9 tap-GEMMs via mma.sync bf16 3-pass split ----
__global__ void __launch_bounds__(256)
conv_hmma(const float* __restrict__ bias, float* __restrict__ out) {
    extern __shared__ char sm[];
    const int tid  = threadIdx.x;
    const int lane = tid & 31, wid = tid >> 5;
    const int b   = blockIdx.x / (HO_ / 2);
    const int oh  = (blockIdx.x - b * (HO_ / 2)) * 2;
    const int pbase  = (wid >> 1) * 32;     // 4 warps along p (128)
    const int cobase = (wid & 1) * 32;      // 2 warps along co (64)

    const uint32_t sA = smem_u32(sm);
    const uint32_t sB = sA + SB_OFF;

    // A: stage 4 input rows (both halves) via cp.async, swizzled.
    // (Pad rows w=128..129 stay uninitialized: they only feed p=126,127,
    //  which the store predicate discards.)
    #pragma unroll
    for (int k = 0; k < 32; k++) {
        int i = tid + k * 256;                 // 0..8191
        int half = i >> 12, rem = i & 4095;
        int row = rem >> 10, rem2 = rem & 1023;
        int w = rem2 >> 3, c = rem2 & 7;
        uint32_t dst = sA + half * A_HALF_BYTES + row * A_ROW_BYTES +
                       w * 128 + ((c ^ (w & 7)) << 4);
        const __nv_bfloat16* g = half ? g_xtl : g_xth;
        const char* src = (const char*)(g + (((size_t)(b * H_ + oh + row)) * W_ + w) * CI_ + c * 8);
        CPA16(dst, src);
    }
    load_b_tap(sB, tid, b, 0, 0);
    CPA_COMMIT();
    CPA_WAIT0();
    __syncthreads();

    // lane constants (identical fragment logic to the passing R10 kernel)
    const int dw = lane & 15, hi = lane >> 4;
    const int bco = (lane & 7) + ((lane >> 3) & 1) * 8;
    const int co0 = cobase + bco,        co1 = co0 + 16;
    const int boff0 = co0 * 128, b7_0 = co0 & 7;
    const int boff1 = co1 * 128, b7_1 = co1 & 7;
    const int aw = pbase + dw;

    float acc[2][2][4][4];
    #pragma unroll
    for (int o = 0; o < 2; o++)
        #pragma unroll
        for (int m = 0; m < 2; m++)
            #pragma unroll
            for (int n = 0; n < 4; n++)
                #pragma unroll
                for (int e = 0; e < 4; e++) acc[o][m][n][e] = 0.f;

    int kh = 0, kw = 0;
    for (int t = 0; t < TAPS; t++) {
        if (t < 8) { load_b_tap(sB, tid, b, t + 1, (t + 1) & 1); CPA_COMMIT(); }

        const int w0 = aw + kw, w1 = w0 + 16;
        const int w07 = w0 & 7, w17 = w1 & 7;
        const uint32_t bb = sB + (t & 1) * B_BUF_BYTES;

        #pragma unroll
        for (int kk = 0; kk < 4; kk++) {
            const int kc = kk * 2 + hi;
            uint32_t bh0[4], bh1[4], bl0[4], bl1[4];
            uint32_t bB0 = bb + boff0 + ((kc ^ b7_0) << 4);
            uint32_t bB1 = bb + boff1 + ((kc ^ b7_1) << 4);
            ldsm4(bB0, bh0);        ldsm4(bB1, bh1);
            ldsm4(bB0 + 8192, bl0); ldsm4(bB1 + 8192, bl1);

            #pragma unroll
            for (int ohl = 0; ohl < 2; ohl++) {
                const uint32_t arow = sA + (kh + ohl) * A_ROW_BYTES;
                const uint32_t a0b = arow + w0 * 128, a1b = arow + w1 * 128;
                uint32_t ah0[4], ah1[4], al0[4], al1[4];
                uint32_t aH0 = a0b + ((kc ^ w07) << 4);
                uint32_t aH1 = a1b + ((kc ^ w17) << 4);
                ldsm4(aH0, ah0);                ldsm4(aH1, ah1);
                ldsm4(aH0 + A_HALF_BYTES, al0); ldsm4(aH1 + A_HALF_BYTES, al1);

                #pragma unroll
                for (int n = 0; n < 4; n++) {
                    const uint32_t* Bh = (n < 2) ? bh0 : bh1;
                    const uint32_t* Bl = (n < 2) ? bl0 : bl1;
                    const int s = n & 1;
                    mma16816(acc[ohl][0][n], ah0, Bh[s], Bh[s + 2]);   // Ah*Bh
                    mma16816(acc[ohl][1][n], ah1, Bh[s], Bh[s + 2]);
                    mma16816(acc[ohl][0][n], al0, Bh[s], Bh[s + 2]);   // Al*Bh
                    mma16816(acc[ohl][1][n], al1, Bh[s], Bh[s + 2]);
                    mma16816(acc[ohl][0][n], ah0, Bl[s], Bl[s + 2]);   // Ah*Bl
                    mma16816(acc[ohl][1][n], ah1, Bl[s], Bl[s + 2]);
                }
            }
        }
        if (t < 8) CPA_WAIT0();
        __syncthreads();
        if (++kw == 3) { kw = 0; ++kh; }
    }

    // epilogue: regs -> smem [ohl][co][p] f32 (reuse A region), coalesced out
    float* smf = (float*)sm;
    const int rowq = lane >> 2, colp = 2 * (lane & 3);
    #pragma unroll
    for (int ohl = 0; ohl < 2; ohl++)
        #pragma unroll
        for (int m = 0; m < 2; m++)
            #pragma unroll
            for (int n = 0; n < 4; n++) {
                int p0 = pbase + m * 16 + rowq;
                int c0 = cobase + n * 8 + colp;
                float* s = smf + ohl * 8192;
                s[c0 * 128 + p0]           = acc[ohl][m][n][0];
                s[(c0 + 1) * 128 + p0]     = acc[ohl][m][n][1];
                s[c0 * 128 + p0 + 8]       = acc[ohl][m][n][2];
                s[(c0 + 1) * 128 + p0 + 8] = acc[ohl][m][n][3];
            }
    __syncthreads();

    const int co = tid >> 2, q = tid & 3;
    const float bv = bias[b * CO_ + co];
    #pragma unroll
    for (int ohl = 0; ohl < 2; ohl++) {
        float* op = out + ((size_t)(b * CO_ + co) * HO_ + oh + ohl) * WO_;
        const float* sp = smf + ohl * 8192 + co * 128;
        #pragma unroll
        for (int i = 0; i < 32; i++) {
            int p = q * 32 + i;
            if (p < WO_) op[p] = sp[p] + bv;
        }
    }
}

extern "C" void kernel_launch(void* const* d_in, const int* in_sizes, int n_in,
                              void* d_out, int out_size) {
    (void)in_sizes; (void)n_in; (void)out_size;
    const float* x    = (const float*)d_in[0];
    const float* wgt  = (const float*)d_in[1];
    const float* bias = (const float*)d_in[2];
    float* out        = (float*)d_out;

    static bool attr_set = false;
    if (!attr_set) {
        cudaFuncSetAttribute(conv_hmma, cudaFuncAttributeMaxDynamicSharedMemorySize,
                             SMEM_BYTES);
        attr_set = true;
    }

    prepass_x<<<B_ * H_, 256>>>(x);
    prepass_w<<<256, 256>>>(wgt);
    conv_hmma<<<B_ * (HO_ / 2), 256, SMEM_BYTES>>>(bias, out);
}

// round 13
// speedup vs baseline: 2.3507x; 1.1456x over previous
#include <cuda_runtime.h>
#include <cuda_bf16.h>
#include <cstdint>

#define B_   16
#define CI_  64
#define CO_  64
#define H_   128
#define W_   128
#define HO_  126
#define WO_  126
#define TAPS 9

// ---- device scratch (static; no allocation APIs) ----
__device__ __nv_bfloat16 g_xth[(size_t)B_ * H_ * W_ * CI_];
__device__ __nv_bfloat16 g_xtl[(size_t)B_ * H_ * W_ * CI_];
__device__ __nv_bfloat16 g_wth[(size_t)B_ * TAPS * CO_ * CI_];
__device__ __nv_bfloat16 g_wtl[(size_t)B_ * TAPS * CO_ * CI_];

// ---- smem layout: p-tile 64, kTile 2 -> 2 CTAs/SM ----
// A: [half 2][row 4][w 66][ci 64] bf16, 128B per w, XOR-swizzled 16B chunks
#define A_WROWS       66
#define A_ROW_BYTES   (A_WROWS * 128)          // 8448
#define A_HALF_BYTES  (4 * A_ROW_BYTES)        // 33792
#define SB_OFF        (2 * A_HALF_BYTES)       // 67584
#define B_BUF_BYTES   16384                    // half(2) * 64co * 128B
#define SMEM_BYTES    (SB_OFF + 2 * B_BUF_BYTES)   // 100352
#define A_CHUNKS      (SB_OFF / 16)            // 4224

// ---- baseline-target PTX helpers ----
__device__ __forceinline__ uint32_t smem_u32(const void* p) {
    uint32_t a;
    asm("{ .reg .u64 t; cvta.to.shared.u64 t, %1; cvt.u32.u64 %0, t; }" : "=r"(a) : "l"(p));
    return a;
}
#define CPA16(dst, src) \
    asm volatile("cp.async.cg.shared.global [%0], [%1], 16;" :: "r"(dst), "l"(src))
#define CPA_COMMIT() asm volatile("cp.async.commit_group;" ::: "memory")
#define CPA_WAIT0()  asm volatile("cp.async.wait_group 0;" ::: "memory")

__device__ __forceinline__ void ldsm4(uint32_t addr, uint32_t r[4]) {
    asm volatile("ldmatrix.sync.aligned.m8n8.x4.shared.b16 {%0,%1,%2,%3}, [%4];"
        : "=r"(r[0]), "=r"(r[1]), "=r"(r[2]), "=r"(r[3]) : "r"(addr));
}
__device__ __forceinline__ void mma16816(float d[4], const uint32_t a[4],
                                         uint32_t b0, uint32_t b1) {
    asm volatile("mma.sync.aligned.m16n8k16.row.col.f32.bf16.bf16.f32 "
        "{%0,%1,%2,%3},{%4,%5,%6,%7},{%8,%9},{%0,%1,%2,%3};"
        : "+f"(d[0]), "+f"(d[1]), "+f"(d[2]), "+f"(d[3])
        : "r"(a[0]), "r"(a[1]), "r"(a[2]), "r"(a[3]), "r"(b0), "r"(b1));
}

// ---- prepass 1: x (B,CI,H,W) f32 -> split bf16 [b*H+h][w][ci] ----
__global__ void __launch_bounds__(256) prepass_x(const float* __restrict__ x) {
    __shared__ float tile[64 * 129];
    const int t = threadIdx.x;
    const int h = blockIdx.x & 127, b = blockIdx.x >> 7;
    const float* xb = x + ((size_t)b * CI_ * H_ + h) * W_;

    #pragma unroll
    for (int j = 0; j < 8; j++) {
        int idx = j * 256 + t;
        int ci = idx >> 5, w4 = (idx & 31) << 2;
        const float4 v = *(const float4*)(xb + (size_t)ci * (H_ * W_) + w4);
        float* dst = tile + ci * 129 + w4;
        dst[0] = v.x; dst[1] = v.y; dst[2] = v.z; dst[3] = v.w;
    }
    __syncthreads();

    const int ci0 = (t & 7) * 8;
    #pragma unroll
    for (int i = 0; i < 4; i++) {
        int w = i * 32 + (t >> 3);
        __nv_bfloat16 hi8[8], lo8[8];
        #pragma unroll
        for (int c = 0; c < 8; c++) {
            float v = tile[(ci0 + c) * 129 + w];
            __nv_bfloat16 hh = __float2bfloat16(v);
            hi8[c] = hh;
            lo8[c] = __float2bfloat16(v - __bfloat162float(hh));
        }
        size_t o = ((size_t)(b * H_ + h) * W_ + w) * CI_ + ci0;
        *(uint4*)(g_xth + o) = *(uint4*)hi8;
        *(uint4*)(g_xtl + o) = *(uint4*)lo8;
    }
}

// ---- prepass 2: weight (B,CO,CI,3,3) f32 -> split bf16 [b*9+t][co][ci] ----
__global__ void prepass_w(const float* __restrict__ wgt) {
    int idx = blockIdx.x * 256 + threadIdx.x;
    int ci = idx & 63, co = (idx >> 6) & 63, b = idx >> 12;
    const float* wp = wgt + (size_t)idx * TAPS;
    #pragma unroll
    for (int t = 0; t < TAPS; t++) {
        float v = wp[t];
        __nv_bfloat16 hh = __float2bfloat16(v);
        size_t o = ((size_t)(b * TAPS + t) * CO_ + co) * CI_ + ci;
        g_wth[o] = hh;
        g_wtl[o] = __float2bfloat16(v - __bfloat162float(hh));
    }
}

// ---- B-tap loader ----
__device__ __forceinline__ void load_b_tap(uint32_t sB, int tid, int b, int t, int buf) {
    #pragma unroll
    for (int k = 0; k < 4; k++) {
        int i = tid + k * 256;
        int half = i >> 9, rem = i & 511;
        int co = rem >> 3, c = rem & 7;
        uint32_t dst = sB + buf * B_BUF_BYTES + half * 8192 +
                       co * 128 + (((c ^ (co & 7)) << 4));
        const __nv_bfloat16* g = half ? g_wtl : g_wth;
        const char* src = (const char*)(g + (((size_t)(b * TAPS + t)) * CO_ + co) * CI_ + c * 8);
        CPA16(dst, src);
    }
}

// ---- main: per (b, 2x oh, w-tile), 9 tap-GEMMs, 3-pass split bf16 ----
__global__ void __launch_bounds__(256, 2)
conv_hmma(const float* __restrict__ bias, float* __restrict__ out) {
    extern __shared__ char sm[];
    const int tid  = threadIdx.x;
    const int lane = tid & 31, wid = tid >> 5;
    const int wt    = blockIdx.x & 1;
    const int rest  = blockIdx.x >> 1;
    const int b     = rest / (HO_ / 2);
    const int oh    = (rest - b * (HO_ / 2)) * 2;
    const int wbase = wt * 62;               // tiles: p 0..63 and p 62..125

    const int cobase = (wid & 1) * 32;        // 2 warps along co
    const int pbase  = ((wid >> 1) & 1) * 32; // 2 warps along p (64)
    const int ohl    = wid >> 2;              // 2 warps along oh

    const uint32_t sA = smem_u32(sm);
    const uint32_t sB = sA + SB_OFF;

    // A: stage 4 input rows x 66 w (both halves), swizzled
    #pragma unroll
    for (int k = 0; k < 17; k++) {
        int i = tid + k * 256;
        if (i < A_CHUNKS) {
            int half = i / 2112, rem = i - half * 2112;
            int row = rem / 528, rem2 = rem - row * 528;
            int w = rem2 >> 3, c = rem2 & 7;
            uint32_t dst = sA + half * A_HALF_BYTES + row * A_ROW_BYTES +
                           w * 128 + ((c ^ (w & 7)) << 4);
            const __nv_bfloat16* g = half ? g_xtl : g_xth;
            const char* src = (const char*)
                (g + (((size_t)(b * H_ + oh + row)) * W_ + wbase + w) * CI_ + c * 8);
            CPA16(dst, src);
        }
    }
    load_b_tap(sB, tid, b, 0, 0);
    CPA_COMMIT();
    CPA_WAIT0();
    __syncthreads();

    // lane constants
    const int dw = lane & 15, hi = lane >> 4;
    const int bco = (lane & 7) + ((lane >> 3) & 1) * 8;
    const int co0 = cobase + bco,        co1 = co0 + 16;
    const int boff0 = co0 * 128, b7_0 = co0 & 7;
    const int boff1 = co1 * 128, b7_1 = co1 & 7;
    const int aw = pbase + dw;

    float acc[2][4][4];
    #pragma unroll
    for (int m = 0; m < 2; m++)
        #pragma unroll
        for (int n = 0; n < 4; n++)
            #pragma unroll
            for (int e = 0; e < 4; e++) acc[m][n][e] = 0.f;

    int kh = 0, kw = 0;
    for (int t = 0; t < TAPS; t++) {
        if (t < 8) { load_b_tap(sB, tid, b, t + 1, (t + 1) & 1); CPA_COMMIT(); }

        const int w0 = aw + kw, w1 = w0 + 16;        // <= 65
        const int w07 = w0 & 7, w17 = w1 & 7;
        const uint32_t arow = sA + (kh + ohl) * A_ROW_BYTES;
        const uint32_t a0b = arow + w0 * 128, a1b = arow + w1 * 128;
        const uint32_t bb = sB + (t & 1) * B_BUF_BYTES;

        #pragma unroll
        for (int kk = 0; kk < 4; kk++) {
            const int kc = kk * 2 + hi;
            uint32_t bh0[4], bh1[4], bl0[4], bl1[4];
            uint32_t bB0 = bb + boff0 + ((kc ^ b7_0) << 4);
            uint32_t bB1 = bb + boff1 + ((kc ^ b7_1) << 4);
            ldsm4(bB0, bh0);        ldsm4(bB1, bh1);
            ldsm4(bB0 + 8192, bl0); ldsm4(bB1 + 8192, bl1);

            uint32_t ah0[4], ah1[4], al0[4], al1[4];
            uint32_t aH0 = a0b + ((kc ^ w07) << 4);
            uint32_t aH1 = a1b + ((kc ^ w17) << 4);
            ldsm4(aH0, ah0);                ldsm4(aH1, ah1);
            ldsm4(aH0 + A_HALF_BYTES, al0); ldsm4(aH1 + A_HALF_BYTES, al1);

            #pragma unroll
            for (int n = 0; n < 4; n++) {
                const uint32_t* Bh = (n < 2) ? bh0 : bh1;
                const uint32_t* Bl = (n < 2) ? bl0 : bl1;
                const int s = n & 1;
                mma16816(acc[0][n], ah0, Bh[s], Bh[s + 2]);   // Ah*Bh
                mma16816(acc[1][n], ah1, Bh[s], Bh[s + 2]);
                mma16816(acc[0][n], al0, Bh[s], Bh[s + 2]);   // Al*Bh
                mma16816(acc[1][n], al1, Bh[s], Bh[s + 2]);
                mma16816(acc[0][n], ah0, Bl[s], Bl[s + 2]);   // Ah*Bl
                mma16816(acc[1][n], ah1, Bl[s], Bl[s + 2]);
            }
        }
        if (t < 8) CPA_WAIT0();
        __syncthreads();
        if (++kw == 3) { kw = 0; ++kh; }
    }

    // epilogue: regs -> smem [ohl][co 64][p 64] f32, then coalesced out
    float* smf = (float*)sm;
    const int rowq = lane >> 2, colp = 2 * (lane & 3);
    float* sw = smf + ohl * 4096;
    #pragma unroll
    for (int m = 0; m < 2; m++)
        #pragma unroll
        for (int n = 0; n < 4; n++) {
            int p0 = pbase + m * 16 + rowq;
            int c0 = cobase + n * 8 + colp;
            sw[c0 * 64 + p0]           = acc[m][n][0];
            sw[(c0 + 1) * 64 + p0]     = acc[m][n][1];
            sw[c0 * 64 + p0 + 8]       = acc[m][n][2];
            sw[(c0 + 1) * 64 + p0 + 8] = acc[m][n][3];
        }
    __syncthreads();

    const int co = tid >> 2, q = tid & 3;
    const float bv = bias[b * CO_ + co];
    #pragma unroll
    for (int o = 0; o < 2; o++) {
        float* op = out + ((size_t)(b * CO_ + co) * HO_ + oh + o) * WO_ + wbase;
        const float* sp = smf + o * 4096 + co * 64;
        #pragma unroll
        for (int i = 0; i < 16; i++) {
            int p = q * 16 + i;            // 0..63; wbase+p <= 125: all valid
            op[p] = sp[p] + bv;
        }
    }
}

extern "C" void kernel_launch(void* const* d_in, const int* in_sizes, int n_in,
                              void* d_out, int out_size) {
    (void)in_sizes; (void)n_in; (void)out_size;
    const float* x    = (const float*)d_in[0];
    const float* wgt  = (const float*)d_in[1];
    const float* bias = (const float*)d_in[2];
    float* out        = (float*)d_out;

    static bool attr_set = false;
    if (!attr_set) {
        cudaFuncSetAttribute(conv_hmma, cudaFuncAttributeMaxDynamicSharedMemorySize,
                             SMEM_BYTES);
        attr_set = true;
    }

    prepass_x<<<B_ * H_, 256>>>(x);
    prepass_w<<<256, 256>>>(wgt);
    conv_hmma<<<2 * B_ * (HO_ / 2), 256, SMEM_BYTES>>>(bias, out);
}

// round 14
// speedup vs baseline: 2.7456x; 1.1680x over previous
#include <cuda_runtime.h>
#include <cuda_fp16.h>
#include <cstdint>

#define B_   16
#define CI_  64
#define CO_  64
#define H_   128
#define W_   128
#define HO_  126
#define WO_  126
#define TAPS 9

// ---- device scratch (static; no allocation APIs) ----
// x split into fp16 hi + fp16 residual; weights single fp16 (error model:
// uncompensated w-rounding 2^-12 -> output rel err ~1e-4 << 1e-3).
__device__ __half g_xh[(size_t)B_ * H_ * W_ * CI_];
__device__ __half g_xl[(size_t)B_ * H_ * W_ * CI_];
__device__ __half g_w[(size_t)B_ * TAPS * CO_ * CI_];

// ---- smem layout: p-tile 64, kTile 2 -> 2 CTAs/SM ----
// A: [half 2][row 4][w 66][ci 64] fp16, 128B per w, XOR-swizzled 16B chunks
#define A_WROWS       66
#define A_ROW_BYTES   (A_WROWS * 128)          // 8448
#define A_HALF_BYTES  (4 * A_ROW_BYTES)        // 33792
#define SB_OFF        (2 * A_HALF_BYTES)       // 67584
#define B_BUF_BYTES   8192                     // 64co * 128B (single fp16)
#define SMEM_BYTES    (SB_OFF + 2 * B_BUF_BYTES)   // 83968
#define A_CHUNKS      (SB_OFF / 16)            // 4224

// ---- baseline-target PTX helpers ----
__device__ __forceinline__ uint32_t smem_u32(const void* p) {
    uint32_t a;
    asm("{ .reg .u64 t; cvta.to.shared.u64 t, %1; cvt.u32.u64 %0, t; }" : "=r"(a) : "l"(p));
    return a;
}
#define CPA16(dst, src) \
    asm volatile("cp.async.cg.shared.global [%0], [%1], 16;" :: "r"(dst), "l"(src))
#define CPA_COMMIT() asm volatile("cp.async.commit_group;" ::: "memory")
#define CPA_WAIT0()  asm volatile("cp.async.wait_group 0;" ::: "memory")

__device__ __forceinline__ void ldsm4(uint32_t addr, uint32_t r[4]) {
    asm volatile("ldmatrix.sync.aligned.m8n8.x4.shared.b16 {%0,%1,%2,%3}, [%4];"
        : "=r"(r[0]), "=r"(r[1]), "=r"(r[2]), "=r"(r[3]) : "r"(addr));
}
__device__ __forceinline__ void mma16816(float d[4], const uint32_t a[4],
                                         uint32_t b0, uint32_t b1) {
    asm volatile("mma.sync.aligned.m16n8k16.row.col.f32.f16.f16.f32 "
        "{%0,%1,%2,%3},{%4,%5,%6,%7},{%8,%9},{%0,%1,%2,%3};"
        : "+f"(d[0]), "+f"(d[1]), "+f"(d[2]), "+f"(d[3])
        : "r"(a[0]), "r"(a[1]), "r"(a[2]), "r"(a[3]), "r"(b0), "r"(b1));
}

// ---- prepass 1: x (B,CI,H,W) f32 -> split fp16 [b*H+h][w][ci] ----
__global__ void __launch_bounds__(256) prepass_x(const float* __restrict__ x) {
    __shared__ float tile[64 * 129];
    const int t = threadIdx.x;
    const int h = blockIdx.x & 127, b = blockIdx.x >> 7;
    const float* xb = x + ((size_t)b * CI_ * H_ + h) * W_;

    #pragma unroll
    for (int j = 0; j < 8; j++) {
        int idx = j * 256 + t;
        int ci = idx >> 5, w4 = (idx & 31) << 2;
        const float4 v = *(const float4*)(xb + (size_t)ci * (H_ * W_) + w4);
        float* dst = tile + ci * 129 + w4;
        dst[0] = v.x; dst[1] = v.y; dst[2] = v.z; dst[3] = v.w;
    }
    __syncthreads();

    const int ci0 = (t & 7) * 8;
    #pragma unroll
    for (int i = 0; i < 4; i++) {
        int w = i * 32 + (t >> 3);
        __half hi8[8], lo8[8];
        #pragma unroll
        for (int c = 0; c < 8; c++) {
            float v = tile[(ci0 + c) * 129 + w];
            __half hh = __float2half(v);
            hi8[c] = hh;
            lo8[c] = __float2half(v - __half2float(hh));
        }
        size_t o = ((size_t)(b * H_ + h) * W_ + w) * CI_ + ci0;
        *(uint4*)(g_xh + o) = *(uint4*)hi8;
        *(uint4*)(g_xl + o) = *(uint4*)lo8;
    }
}

// ---- prepass 2: weight (B,CO,CI,3,3) f32 -> fp16 [b*9+t][co][ci] ----
__global__ void prepass_w(const float* __restrict__ wgt) {
    int idx = blockIdx.x * 256 + threadIdx.x;
    int ci = idx & 63, co = (idx >> 6) & 63, b = idx >> 12;
    const float* wp = wgt + (size_t)idx * TAPS;
    #pragma unroll
    for (int t = 0; t < TAPS; t++) {
        size_t o = ((size_t)(b * TAPS + t) * CO_ + co) * CI_ + ci;
        g_w[o] = __float2half(wp[t]);
    }
}

// ---- B-tap loader: g_w[b*9+t][co][ci] -> swizzled smem buf (8 KB) ----
__device__ __forceinline__ void load_b_tap(uint32_t sB, int tid, int b, int t, int buf) {
    #pragma unroll
    for (int k = 0; k < 2; k++) {
        int i = tid + k * 256;                 // 0..511
        int co = i >> 3, c = i & 7;
        uint32_t dst = sB + buf * B_BUF_BYTES +
                       co * 128 + (((c ^ (co & 7)) << 4));
        const char* src = (const char*)
            (g_w + (((size_t)(b * TAPS + t)) * CO_ + co) * CI_ + c * 8);
        CPA16(dst, src);
    }
}

// ---- main: per (b, 2x oh, w-tile), 9 tap-GEMMs, 2-pass fp16 split ----
__global__ void __launch_bounds__(256, 2)
conv_hmma(const float* __restrict__ bias, float* __restrict__ out) {
    extern __shared__ char sm[];
    const int tid  = threadIdx.x;
    const int lane = tid & 31, wid = tid >> 5;
    const int wt    = blockIdx.x & 1;
    const int rest  = blockIdx.x >> 1;
    const int b     = rest / (HO_ / 2);
    const int oh    = (rest - b * (HO_ / 2)) * 2;
    const int wbase = wt * 62;               // tiles: p 0..63 and p 62..125

    const int cobase = (wid & 1) * 32;        // 2 warps along co
    const int pbase  = ((wid >> 1) & 1) * 32; // 2 warps along p (64)
    const int ohl    = wid >> 2;              // 2 warps along oh

    const uint32_t sA = smem_u32(sm);
    const uint32_t sB = sA + SB_OFF;

    // A: stage 4 input rows x 66 w (hi + lo halves), swizzled
    #pragma unroll
    for (int k = 0; k < 17; k++) {
        int i = tid + k * 256;
        if (i < A_CHUNKS) {
            int half = i / 2112, rem = i - half * 2112;
            int row = rem / 528, rem2 = rem - row * 528;
            int w = rem2 >> 3, c = rem2 & 7;
            uint32_t dst = sA + half * A_HALF_BYTES + row * A_ROW_BYTES +
                           w * 128 + ((c ^ (w & 7)) << 4);
            const __half* g = half ? g_xl : g_xh;
            const char* src = (const char*)
                (g + (((size_t)(b * H_ + oh + row)) * W_ + wbase + w) * CI_ + c * 8);
            CPA16(dst, src);
        }
    }
    load_b_tap(sB, tid, b, 0, 0);
    CPA_COMMIT();
    CPA_WAIT0();
    __syncthreads();

    // lane constants (fragment logic identical to passing R13 kernel)
    const int dw = lane & 15, hi = lane >> 4;
    const int bco = (lane & 7) + ((lane >> 3) & 1) * 8;
    const int co0 = cobase + bco,        co1 = co0 + 16;
    const int boff0 = co0 * 128, b7_0 = co0 & 7;
    const int boff1 = co1 * 128, b7_1 = co1 & 7;
    const int aw = pbase + dw;

    float acc[2][4][4];
    #pragma unroll
    for (int m = 0; m < 2; m++)
        #pragma unroll
        for (int n = 0; n < 4; n++)
            #pragma unroll
            for (int e = 0; e < 4; e++) acc[m][n][e] = 0.f;

    int kh = 0, kw = 0;
    for (int t = 0; t < TAPS; t++) {
        if (t < 8) { load_b_tap(sB, tid, b, t + 1, (t + 1) & 1); CPA_COMMIT(); }

        const int w0 = aw + kw, w1 = w0 + 16;        // <= 65
        const int w07 = w0 & 7, w17 = w1 & 7;
        const uint32_t arow = sA + (kh + ohl) * A_ROW_BYTES;
        const uint32_t a0b = arow + w0 * 128, a1b = arow + w1 * 128;
        const uint32_t bb = sB + (t & 1) * B_BUF_BYTES;

        #pragma unroll
        for (int kk = 0; kk < 4; kk++) {
            const int kc = kk * 2 + hi;
            uint32_t bh0[4], bh1[4];
            ldsm4(bb + boff0 + ((kc ^ b7_0) << 4), bh0);
            ldsm4(bb + boff1 + ((kc ^ b7_1) << 4), bh1);

            uint32_t ah0[4], ah1[4], al0[4], al1[4];
            uint32_t aH0 = a0b + ((kc ^ w07) << 4);
            uint32_t aH1 = a1b + ((kc ^ w17) << 4);
            ldsm4(aH0, ah0);                ldsm4(aH1, ah1);
            ldsm4(aH0 + A_HALF_BYTES, al0); ldsm4(aH1 + A_HALF_BYTES, al1);

            #pragma unroll
            for (int n = 0; n < 4; n++) {
                const uint32_t* Bh = (n < 2) ? bh0 : bh1;
                const int s = n & 1;
                mma16816(acc[0][n], ah0, Bh[s], Bh[s + 2]);   // Ah*B
                mma16816(acc[1][n], ah1, Bh[s], Bh[s + 2]);
                mma16816(acc[0][n], al0, Bh[s], Bh[s + 2]);   // Al*B
                mma16816(acc[1][n], al1, Bh[s], Bh[s + 2]);
            }
        }
        if (t < 8) CPA_WAIT0();
        __syncthreads();
        if (++kw == 3) { kw = 0; ++kh; }
    }

    // epilogue: regs -> smem [ohl][co 64][p 64] f32, then coalesced out
    float* smf = (float*)sm;
    const int rowq = lane >> 2, colp = 2 * (lane & 3);
    float* sw = smf + ohl * 4096;
    #pragma unroll
    for (int m = 0; m < 2; m++)
        #pragma unroll
        for (int n = 0; n < 4; n++) {
            int p0 = pbase + m * 16 + rowq;
            int c0 = cobase + n * 8 + colp;
            sw[c0 * 64 + p0]           = acc[m][n][0];
            sw[(c0 + 1) * 64 + p0]     = acc[m][n][1];
            sw[c0 * 64 + p0 + 8]       = acc[m][n][2];
            sw[(c0 + 1) * 64 + p0 + 8] = acc[m][n][3];
        }
    __syncthreads();

    const int co = tid >> 2, q = tid & 3;
    const float bv = bias[b * CO_ + co];
    #pragma unroll
    for (int o = 0; o < 2; o++) {
        float* op = out + ((size_t)(b * CO_ + co) * HO_ + oh + o) * WO_ + wbase;
        const float* sp = smf + o * 4096 + co * 64;
        #pragma unroll
        for (int i = 0; i < 16; i++) {
            int p = q * 16 + i;            // wbase+p <= 125: all valid
            op[p] = sp[p] + bv;
        }
    }
}

extern "C" void kernel_launch(void* const* d_in, const int* in_sizes, int n_in,
                              void* d_out, int out_size) {
    (void)in_sizes; (void)n_in; (void)out_size;
    const float* x    = (const float*)d_in[0];
    const float* wgt  = (const float*)d_in[1];
    const float* bias = (const float*)d_in[2];
    float* out        = (float*)d_out;

    static bool attr_set = false;
    if (!attr_set) {
        cudaFuncSetAttribute(conv_hmma, cudaFuncAttributeMaxDynamicSharedMemorySize,
                             SMEM_BYTES);
        attr_set = true;
    }

    prepass_x<<<B_ * H_, 256>>>(x);
    prepass_w<<<256, 256>>>(wgt);
    conv_hmma<<<2 * B_ * (HO_ / 2), 256, SMEM_BYTES>>>(bias, out);
}

// round 15
// speedup vs baseline: 3.7302x; 1.3586x over previous
#include <cuda_runtime.h>
#include <cuda_fp16.h>
#include <cstdint>

#define B_   16
#define CI_  64
#define CO_  64
#define H_   128
#define W_   128
#define HO_  126
#define WO_  126
#define TAPS 9

// ---- device scratch (static; no allocation APIs) ----
// Single-pass fp16: x and w both rounded to fp16, f32 accumulation.
// Error model (validated R14): each rounding contributes ~1.6e-4 RMS rel;
// combined ~2.2e-4 << 1e-3.
__device__ __half g_xh[(size_t)B_ * H_ * W_ * CI_];
__device__ __half g_w[(size_t)B_ * TAPS * CO_ * CI_];

// ---- smem layout: p-tile 64, kTile 2 ----
// A: [row 4][w 66][ci 64] fp16, 128B per w, XOR-swizzled 16B chunks
#define A_WROWS       66
#define A_ROW_BYTES   (A_WROWS * 128)          // 8448
#define SB_OFF        (4 * A_ROW_BYTES)        // 33792
#define B_BUF_BYTES   8192                     // 64co * 128B
#define SMEM_BYTES    (SB_OFF + 2 * B_BUF_BYTES)   // 50176 -> up to 4 CTA/SM by smem
#define A_CHUNKS      (SB_OFF / 16)            // 2112

// ---- baseline-target PTX helpers ----
__device__ __forceinline__ uint32_t smem_u32(const void* p) {
    uint32_t a;
    asm("{ .reg .u64 t; cvta.to.shared.u64 t, %1; cvt.u32.u64 %0, t; }" : "=r"(a) : "l"(p));
    return a;
}
#define CPA16(dst, src) \
    asm volatile("cp.async.cg.shared.global [%0], [%1], 16;" :: "r"(dst), "l"(src))
#define CPA_COMMIT() asm volatile("cp.async.commit_group;" ::: "memory")
#define CPA_WAIT0()  asm volatile("cp.async.wait_group 0;" ::: "memory")

__device__ __forceinline__ void ldsm4(uint32_t addr, uint32_t r[4]) {
    asm volatile("ldmatrix.sync.aligned.m8n8.x4.shared.b16 {%0,%1,%2,%3}, [%4];"
        : "=r"(r[0]), "=r"(r[1]), "=r"(r[2]), "=r"(r[3]) : "r"(addr));
}
__device__ __forceinline__ void mma16816(float d[4], const uint32_t a[4],
                                         uint32_t b0, uint32_t b1) {
    asm volatile("mma.sync.aligned.m16n8k16.row.col.f32.f16.f16.f32 "
        "{%0,%1,%2,%3},{%4,%5,%6,%7},{%8,%9},{%0,%1,%2,%3};"
        : "+f"(d[0]), "+f"(d[1]), "+f"(d[2]), "+f"(d[3])
        : "r"(a[0]), "r"(a[1]), "r"(a[2]), "r"(a[3]), "r"(b0), "r"(b1));
}

// ---- prepass 1: x (B,CI,H,W) f32 -> fp16 [b*H+h][w][ci] ----
__global__ void __launch_bounds__(256) prepass_x(const float* __restrict__ x) {
    __shared__ float tile[64 * 129];
    const int t = threadIdx.x;
    const int h = blockIdx.x & 127, b = blockIdx.x >> 7;
    const float* xb = x + ((size_t)b * CI_ * H_ + h) * W_;

    #pragma unroll
    for (int j = 0; j < 8; j++) {
        int idx = j * 256 + t;
        int ci = idx >> 5, w4 = (idx & 31) << 2;
        const float4 v = *(const float4*)(xb + (size_t)ci * (H_ * W_) + w4);
        float* dst = tile + ci * 129 + w4;
        dst[0] = v.x; dst[1] = v.y; dst[2] = v.z; dst[3] = v.w;
    }
    __syncthreads();

    const int ci0 = (t & 7) * 8;
    #pragma unroll
    for (int i = 0; i < 4; i++) {
        int w = i * 32 + (t >> 3);
        __half h8[8];
        #pragma unroll
        for (int c = 0; c < 8; c++)
            h8[c] = __float2half(tile[(ci0 + c) * 129 + w]);
        size_t o = ((size_t)(b * H_ + h) * W_ + w) * CI_ + ci0;
        *(uint4*)(g_xh + o) = *(uint4*)h8;
    }
}

// ---- prepass 2: weight (B,CO,CI,3,3) f32 -> fp16 [b*9+t][co][ci] ----
__global__ void prepass_w(const float* __restrict__ wgt) {
    int idx = blockIdx.x * 256 + threadIdx.x;
    int ci = idx & 63, co = (idx >> 6) & 63, b = idx >> 12;
    const float* wp = wgt + (size_t)idx * TAPS;
    #pragma unroll
    for (int t = 0; t < TAPS; t++) {
        size_t o = ((size_t)(b * TAPS + t) * CO_ + co) * CI_ + ci;
        g_w[o] = __float2half(wp[t]);
    }
}

// ---- B-tap loader: g_w[b*9+t][co][ci] -> swizzled smem buf (8 KB) ----
__device__ __forceinline__ void load_b_tap(uint32_t sB, int tid, int b, int t, int buf) {
    #pragma unroll
    for (int k = 0; k < 2; k++) {
        int i = tid + k * 256;                 // 0..511
        int co = i >> 3, c = i & 7;
        uint32_t dst = sB + buf * B_BUF_BYTES +
                       co * 128 + (((c ^ (co & 7)) << 4));
        const char* src = (const char*)
            (g_w + (((size_t)(b * TAPS + t)) * CO_ + co) * CI_ + c * 8);
        CPA16(dst, src);
    }
}

// ---- main: per (b, 2x oh, w-tile), 9 tap-GEMMs, single-pass fp16 ----
__global__ void __launch_bounds__(256, 2)
conv_hmma(const float* __restrict__ bias, float* __restrict__ out) {
    extern __shared__ char sm[];
    const int tid  = threadIdx.x;
    const int lane = tid & 31, wid = tid >> 5;
    const int wt    = blockIdx.x & 1;
    const int rest  = blockIdx.x >> 1;
    const int b     = rest / (HO_ / 2);
    const int oh    = (rest - b * (HO_ / 2)) * 2;
    const int wbase = wt * 62;               // tiles: p 0..63 and p 62..125

    const int cobase = (wid & 1) * 32;        // 2 warps along co
    const int pbase  = ((wid >> 1) & 1) * 32; // 2 warps along p (64)
    const int ohl    = wid >> 2;              // 2 warps along oh

    const uint32_t sA = smem_u32(sm);
    const uint32_t sB = sA + SB_OFF;

    // A: stage 4 input rows x 66 w, swizzled
    #pragma unroll
    for (int k = 0; k < 9; k++) {
        int i = tid + k * 256;
        if (i < A_CHUNKS) {
            int row = i / 528, rem2 = i - row * 528;
            int w = rem2 >> 3, c = rem2 & 7;
            uint32_t dst = sA + row * A_ROW_BYTES +
                           w * 128 + ((c ^ (w & 7)) << 4);
            const char* src = (const char*)
                (g_xh + (((size_t)(b * H_ + oh + row)) * W_ + wbase + w) * CI_ + c * 8);
            CPA16(dst, src);
        }
    }
    load_b_tap(sB, tid, b, 0, 0);
    CPA_COMMIT();
    CPA_WAIT0();
    __syncthreads();

    // lane constants (fragment logic identical to passing R13/R14 kernels)
    const int dw = lane & 15, hi = lane >> 4;
    const int bco = (lane & 7) + ((lane >> 3) & 1) * 8;
    const int co0 = cobase + bco,        co1 = co0 + 16;
    const int boff0 = co0 * 128, b7_0 = co0 & 7;
    const int boff1 = co1 * 128, b7_1 = co1 & 7;
    const int aw = pbase + dw;

    float acc[2][4][4];
    #pragma unroll
    for (int m = 0; m < 2; m++)
        #pragma unroll
        for (int n = 0; n < 4; n++)
            #pragma unroll
            for (int e = 0; e < 4; e++) acc[m][n][e] = 0.f;

    int kh = 0, kw = 0;
    for (int t = 0; t < TAPS; t++) {
        if (t < 8) { load_b_tap(sB, tid, b, t + 1, (t + 1) & 1); CPA_COMMIT(); }

        const int w0 = aw + kw, w1 = w0 + 16;        // <= 65
        const int w07 = w0 & 7, w17 = w1 & 7;
        const uint32_t arow = sA + (kh + ohl) * A_ROW_BYTES;
        const uint32_t a0b = arow + w0 * 128, a1b = arow + w1 * 128;
        const uint32_t bb = sB + (t & 1) * B_BUF_BYTES;

        #pragma unroll
        for (int kk = 0; kk < 4; kk++) {
            const int kc = kk * 2 + hi;
            uint32_t bh0[4], bh1[4];
            ldsm4(bb + boff0 + ((kc ^ b7_0) << 4), bh0);
            ldsm4(bb + boff1 + ((kc ^ b7_1) << 4), bh1);

            uint32_t ah0[4], ah1[4];
            ldsm4(a0b + ((kc ^ w07) << 4), ah0);
            ldsm4(a1b + ((kc ^ w17) << 4), ah1);

            #pragma unroll
            for (int n = 0; n < 4; n++) {
                const uint32_t* Bh = (n < 2) ? bh0 : bh1;
                const int s = n & 1;
                mma16816(acc[0][n], ah0, Bh[s], Bh[s + 2]);
                mma16816(acc[1][n], ah1, Bh[s], Bh[s + 2]);
            }
        }
        if (t < 8) CPA_WAIT0();
        __syncthreads();
        if (++kw == 3) { kw = 0; ++kh; }
    }

    // epilogue: regs -> smem [ohl][co 64][p 64] f32, then coalesced out
    float* smf = (float*)sm;
    const int rowq = lane >> 2, colp = 2 * (lane & 3);
    float* sw = smf + ohl * 4096;
    #pragma unroll
    for (int m = 0; m < 2; m++)
        #pragma unroll
        for (int n = 0; n < 4; n++) {
            int p0 = pbase + m * 16 + rowq;
            int c0 = cobase + n * 8 + colp;
            sw[c0 * 64 + p0]           = acc[m][n][0];
            sw[(c0 + 1) * 64 + p0]     = acc[m][n][1];
            sw[c0 * 64 + p0 + 8]       = acc[m][n][2];
            sw[(c0 + 1) * 64 + p0 + 8] = acc[m][n][3];
        }
    __syncthreads();

    const int co = tid >> 2, q = tid & 3;
    const float bv = bias[b * CO_ + co];
    #pragma unroll
    for (int o = 0; o < 2; o++) {
        float* op = out + ((size_t)(b * CO_ + co) * HO_ + oh + o) * WO_ + wbase;
        const float* sp = smf + o * 4096 + co * 64;
        #pragma unroll
        for (int i = 0; i < 16; i++) {
            int p = q * 16 + i;            // wbase+p <= 125: all valid
            op[p] = sp[p] + bv;
        }
    }
}

extern "C" void kernel_launch(void* const* d_in, const int* in_sizes, int n_in,
                              void* d_out, int out_size) {
    (void)in_sizes; (void)n_in; (void)out_size;
    const float* x    = (const float*)d_in[0];
    const float* wgt  = (const float*)d_in[1];
    const float* bias = (const float*)d_in[2];
    float* out        = (float*)d_out;

    static bool attr_set = false;
    if (!attr_set) {
        cudaFuncSetAttribute(conv_hmma, cudaFuncAttributeMaxDynamicSharedMemorySize,
                             SMEM_BYTES);
        attr_set = true;
    }

    prepass_x<<<B_ * H_, 256>>>(x);
    prepass_w<<<256, 256>>>(wgt);
    conv_hmma<<<2 * B_ * (HO_ / 2), 256, SMEM_BYTES>>>(bias, out);
}

// round 16
// speedup vs baseline: 3.8484x; 1.0317x over previous
#include <cuda_runtime.h>
#include <cuda_fp16.h>
#include <cstdint>

#define B_   16
#define CI_  64
#define CO_  64
#define H_   128
#define W_   128
#define HO_  126
#define WO_  126
#define TAPS 9

// ---- device scratch (static; no allocation APIs) ----
// Single-pass fp16 (validated: rel_err 2.23e-4 << 1e-3).
__device__ __half g_xh[(size_t)B_ * H_ * W_ * CI_];
__device__ __half g_w[(size_t)B_ * TAPS * CO_ * CI_];

// ---- smem layout: p-tile 64, kTile 2; ALL taps resident ----
// A: [row 4][w 66][ci 64] fp16, 128B per w, XOR-swizzled 16B chunks
// B: [tap 9][co 64][ci 64] fp16, same swizzle, 8 KB per tap
#define A_WROWS       66
#define A_ROW_BYTES   (A_WROWS * 128)          // 8448
#define SB_OFF        (4 * A_ROW_BYTES)        // 33792
#define B_TAP_BYTES   8192
#define SMEM_BYTES    (SB_OFF + TAPS * B_TAP_BYTES)   // 107520 -> 2 CTAs/SM
#define A_CHUNKS      (SB_OFF / 16)            // 2112

// ---- baseline-target PTX helpers ----
__device__ __forceinline__ uint32_t smem_u32(const void* p) {
    uint32_t a;
    asm("{ .reg .u64 t; cvta.to.shared.u64 t, %1; cvt.u32.u64 %0, t; }" : "=r"(a) : "l"(p));
    return a;
}
#define CPA16(dst, src) \
    asm volatile("cp.async.cg.shared.global [%0], [%1], 16;" :: "r"(dst), "l"(src))
#define CPA_COMMIT() asm volatile("cp.async.commit_group;" ::: "memory")
#define CPA_WAIT0()  asm volatile("cp.async.wait_group 0;" ::: "memory")

__device__ __forceinline__ void ldsm4(uint32_t addr, uint32_t r[4]) {
    asm volatile("ldmatrix.sync.aligned.m8n8.x4.shared.b16 {%0,%1,%2,%3}, [%4];"
        : "=r"(r[0]), "=r"(r[1]), "=r"(r[2]), "=r"(r[3]) : "r"(addr));
}
__device__ __forceinline__ void mma16816(float d[4], const uint32_t a[4],
                                         uint32_t b0, uint32_t b1) {
    asm volatile("mma.sync.aligned.m16n8k16.row.col.f32.f16.f16.f32 "
        "{%0,%1,%2,%3},{%4,%5,%6,%7},{%8,%9},{%0,%1,%2,%3};"
        : "+f"(d[0]), "+f"(d[1]), "+f"(d[2]), "+f"(d[3])
        : "r"(a[0]), "r"(a[1]), "r"(a[2]), "r"(a[3]), "r"(b0), "r"(b1));
}

// ---- prepass 1: x (B,CI,H,W) f32 -> fp16 [b*H+h][w][ci] ----
__global__ void __launch_bounds__(256) prepass_x(const float* __restrict__ x) {
    __shared__ float tile[64 * 129];
    const int t = threadIdx.x;
    const int h = blockIdx.x & 127, b = blockIdx.x >> 7;
    const float* xb = x + ((size_t)b * CI_ * H_ + h) * W_;

    #pragma unroll
    for (int j = 0; j < 8; j++) {
        int idx = j * 256 + t;
        int ci = idx >> 5, w4 = (idx & 31) << 2;
        const float4 v = *(const float4*)(xb + (size_t)ci * (H_ * W_) + w4);
        float* dst = tile + ci * 129 + w4;
        dst[0] = v.x; dst[1] = v.y; dst[2] = v.z; dst[3] = v.w;
    }
    __syncthreads();

    const int ci0 = (t & 7) * 8;
    #pragma unroll
    for (int i = 0; i < 4; i++) {
        int w = i * 32 + (t >> 3);
        __half h8[8];
        #pragma unroll
        for (int c = 0; c < 8; c++)
            h8[c] = __float2half(tile[(ci0 + c) * 129 + w]);
        size_t o = ((size_t)(b * H_ + h) * W_ + w) * CI_ + ci0;
        *(uint4*)(g_xh + o) = *(uint4*)h8;
    }
}

// ---- prepass 2: weight (B,CO,CI,3,3) f32 -> fp16 [b*9+t][co][ci] ----
__global__ void prepass_w(const float* __restrict__ wgt) {
    int idx = blockIdx.x * 256 + threadIdx.x;
    int ci = idx & 63, co = (idx >> 6) & 63, b = idx >> 12;
    const float* wp = wgt + (size_t)idx * TAPS;
    #pragma unroll
    for (int t = 0; t < TAPS; t++) {
        size_t o = ((size_t)(b * TAPS + t) * CO_ + co) * CI_ + ci;
        g_w[o] = __float2half(wp[t]);
    }
}

// ---- main: per (b, 2x oh, w-tile); barrier-free mainloop ----
__global__ void __launch_bounds__(256, 2)
conv_hmma(const float* __restrict__ bias, float* __restrict__ out) {
    extern __shared__ char sm[];
    const int tid  = threadIdx.x;
    const int lane = tid & 31, wid = tid >> 5;
    const int wt    = blockIdx.x & 1;
    const int rest  = blockIdx.x >> 1;
    const int b     = rest / (HO_ / 2);
    const int oh    = (rest - b * (HO_ / 2)) * 2;
    const int wbase = wt * 62;               // tiles: p 0..63 and p 62..125

    const int cobase = (wid & 1) * 32;        // 2 warps along co
    const int pbase  = ((wid >> 1) & 1) * 32; // 2 warps along p (64)
    const int ohl    = wid >> 2;              // 2 warps along oh

    const uint32_t sA = smem_u32(sm);
    const uint32_t sB = sA + SB_OFF;

    // ---- single prologue: A tile + ALL 9 B taps, one wait, one barrier ----
    #pragma unroll
    for (int k = 0; k < 9; k++) {
        int i = tid + k * 256;
        if (i < A_CHUNKS) {
            int row = i / 528, rem2 = i - row * 528;
            int w = rem2 >> 3, c = rem2 & 7;
            uint32_t dst = sA + row * A_ROW_BYTES +
                           w * 128 + ((c ^ (w & 7)) << 4);
            const char* src = (const char*)
                (g_xh + (((size_t)(b * H_ + oh + row)) * W_ + wbase + w) * CI_ + c * 8);
            CPA16(dst, src);
        }
    }
    {
        const __half* gw = g_w + (size_t)b * TAPS * CO_ * CI_;
        #pragma unroll
        for (int k = 0; k < 18; k++) {
            int i = tid + k * 256;                 // 0..4607 = tap*512 + co*8 + c
            int t = i >> 9, rem = i & 511;
            int co = rem >> 3, c = rem & 7;
            uint32_t dst = sB + t * B_TAP_BYTES +
                           co * 128 + (((c ^ (co & 7)) << 4));
            CPA16(dst, (const char*)(gw + ((size_t)t * CO_ + co) * CI_ + c * 8));
        }
    }
    CPA_COMMIT();
    CPA_WAIT0();
    __syncthreads();

    // lane constants (fragment logic identical to passing R15 kernel)
    const int dw = lane & 15, hi = lane >> 4;
    const int bco = (lane & 7) + ((lane >> 3) & 1) * 8;
    const int co0 = cobase + bco,        co1 = co0 + 16;
    const int boff0 = co0 * 128, b7_0 = co0 & 7;
    const int boff1 = co1 * 128, b7_1 = co1 & 7;
    const int aw = pbase + dw;

    float acc[2][4][4];
    #pragma unroll
    for (int m = 0; m < 2; m++)
        #pragma unroll
        for (int n = 0; n < 4; n++)
            #pragma unroll
            for (int e = 0; e < 4; e++) acc[m][n][e] = 0.f;

    // ---- barrier-free mainloop: 9 taps x 4 kk x 8 mma ----
    #pragma unroll
    for (int t = 0; t < TAPS; t++) {
        const int kh = t / 3, kw = t % 3;
        const int w0 = aw + kw, w1 = w0 + 16;        // <= 65
        const int w07 = w0 & 7, w17 = w1 & 7;
        const uint32_t arow = sA + (kh + ohl) * A_ROW_BYTES;
        const uint32_t a0b = arow + w0 * 128, a1b = arow + w1 * 128;
        const uint32_t bb = sB + t * B_TAP_BYTES;

        #pragma unroll
        for (int kk = 0; kk < 4; kk++) {
            const int kc = kk * 2 + hi;
            uint32_t bh0[4], bh1[4];
            ldsm4(bb + boff0 + ((kc ^ b7_0) << 4), bh0);
            ldsm4(bb + boff1 + ((kc ^ b7_1) << 4), bh1);

            uint32_t ah0[4], ah1[4];
            ldsm4(a0b + ((kc ^ w07) << 4), ah0);
            ldsm4(a1b + ((kc ^ w17) << 4), ah1);

            #pragma unroll
            for (int n = 0; n < 4; n++) {
                const uint32_t* Bh = (n < 2) ? bh0 : bh1;
                const int s = n & 1;
                mma16816(acc[0][n], ah0, Bh[s], Bh[s + 2]);
                mma16816(acc[1][n], ah1, Bh[s], Bh[s + 2]);
            }
        }
    }

    // epilogue: regs -> smem [ohl][co 64][p 64] f32, then coalesced out
    __syncthreads();   // all ldsm reads done before smem reuse
    float* smf = (float*)sm;
    const int rowq = lane >> 2, colp = 2 * (lane & 3);
    float* sw = smf + ohl * 4096;
    #pragma unroll
    for (int m = 0; m < 2; m++)
        #pragma unroll
        for (int n = 0; n < 4; n++) {
            int p0 = pbase + m * 16 + rowq;
            int c0 = cobase + n * 8 + colp;
            sw[c0 * 64 + p0]           = acc[m][n][0];
            sw[(c0 + 1) * 64 + p0]     = acc[m][n][1];
            sw[c0 * 64 + p0 + 8]       = acc[m][n][2];
            sw[(c0 + 1) * 64 + p0 + 8] = acc[m][n][3];
        }
    __syncthreads();

    const int co = tid >> 2, q = tid & 3;
    const float bv = bias[b * CO_ + co];
    #pragma unroll
    for (int o = 0; o < 2; o++) {
        float* op = out + ((size_t)(b * CO_ + co) * HO_ + oh + o) * WO_ + wbase;
        const float* sp = smf + o * 4096 + co * 64;
        #pragma unroll
        for (int i = 0; i < 16; i++) {
            int p = q * 16 + i;            // wbase+p <= 125: all valid
            op[p] = sp[p] + bv;
        }
    }
}

extern "C" void kernel_launch(void* const* d_in, const int* in_sizes, int n_in,
                              void* d_out, int out_size) {
    (void)in_sizes; (void)n_in; (void)out_size;
    const float* x    = (const float*)d_in[0];
    const float* wgt  = (const float*)d_in[1];
    const float* bias = (const float*)d_in[2];
    float* out        = (float*)d_out;

    static bool attr_set = false;
    if (!attr_set) {
        cudaFuncSetAttribute(conv_hmma, cudaFuncAttributeMaxDynamicSharedMemorySize,
                             SMEM_BYTES);
        attr_set = true;
    }

    prepass_x<<<B_ * H_, 256>>>(x);
    prepass_w<<<256, 256>>>(wgt);
    conv_hmma<<<2 * B_ * (HO_ / 2), 256, SMEM_BYTES>>>(bias, out);
}